// round 9
// baseline (speedup 1.0000x reference)
#include <cuda_runtime.h>
#include <cuda_bf16.h>
#include <cstdint>

#define BBATCH 16
#define CCH    256
#define HHH    48
#define WWW    48
#define NPIX   2304
#define KCONV  2304
#define EPSB   1e-5f

#define BMT 128
#define BNT 64
#define BKT 32

#define AK_PAD 40     // A [m][k] rows: 40 bf16 = 80B
#define AM_PAD 136    // A [k][m] rows (TA): 272B
#define BN_PAD 72     // B [k][n] rows: 144B

typedef __nv_bfloat16 bf16;

// ---------------- scratch ----------------
#define FSZ  ((size_t)BBATCH * CCH * NPIX)
#define ASZG ((size_t)BBATCH * NPIX * NPIX)

__device__ float g_scores[ASZG];
__device__ float g_fused [FSZ];

__device__ __align__(16) bf16 g_Fbh[FSZ], g_Fbl[FSZ], g_Fah[FSZ], g_Fal[FSZ];
__device__ __align__(16) bf16 g_qwh[CCH*CCH], g_qwl[CCH*CCH];
__device__ __align__(16) bf16 g_kwh[CCH*CCH], g_kwl[CCH*CCH];
__device__ __align__(16) bf16 g_vwh[CCH*CCH], g_vwl[CCH*CCH];
__device__ __align__(16) bf16 g_c1h[CCH*KCONV], g_c1l[CCH*KCONV];
__device__ __align__(16) bf16 g_c2h[CCH*KCONV], g_c2l[CCH*KCONV];
__device__ __align__(16) bf16 g_Qh[FSZ], g_Ql[FSZ], g_Kh[FSZ], g_Kl[FSZ];
__device__ __align__(16) bf16 g_Vh[FSZ], g_Vl[FSZ];
__device__ __align__(16) bf16 g_Ath[ASZG], g_Atl[ASZG];
__device__ __align__(16) bf16 g_Fh[FSZ], g_Fl[FSZ];
__device__ __align__(16) bf16 g_th[FSZ], g_tl[FSZ];

// ---------------- helpers ----------------
__device__ __forceinline__ uint32_t smem_u32(const void* p) {
    uint32_t a;
    asm("{ .reg .u64 t; cvta.to.shared.u64 t, %1; cvt.u32.u64 %0, t; }"
        : "=r"(a) : "l"(p));
    return a;
}
__device__ __forceinline__ uint32_t pk(bf16 a, bf16 b) {
    return (uint32_t)__bfloat16_as_ushort(a) |
           ((uint32_t)__bfloat16_as_ushort(b) << 16);
}
__device__ __forceinline__ void spl(float x, bf16& h, bf16& l) {
    h = __float2bfloat16(x);
    l = __float2bfloat16(x - __bfloat162float(h));
}
__device__ __forceinline__ void wr_bf(bf16* H, bf16* L, size_t off,
                                      float a, float b) {
    bf16 h0, l0, h1, l1;
    spl(a, h0, l0); spl(b, h1, l1);
    *(uint32_t*)(H + off) = pk(h0, h1);
    *(uint32_t*)(L + off) = pk(l0, l1);
}

#define CPA(d, s)     asm volatile("cp.async.cg.shared.global [%0], [%1], 16;" :: "r"(d), "l"(s))
#define CPA_COMMIT()  asm volatile("cp.async.commit_group;")
#define CPA_WAIT0()   asm volatile("cp.async.wait_group 0;")
#define CPA_WAIT1()   asm volatile("cp.async.wait_group 1;")

#define LDMX4(R, addr) \
    asm volatile("ldmatrix.sync.aligned.m8n8.x4.shared.b16 {%0,%1,%2,%3}, [%4];" \
        : "=r"((R)[0]), "=r"((R)[1]), "=r"((R)[2]), "=r"((R)[3]) : "r"(addr))
#define LDMX4T(R, addr) \
    asm volatile("ldmatrix.sync.aligned.m8n8.x4.trans.shared.b16 {%0,%1,%2,%3}, [%4];" \
        : "=r"((R)[0]), "=r"((R)[1]), "=r"((R)[2]), "=r"((R)[3]) : "r"(addr))
#define MMA16816(d, a, b) \
    asm volatile("mma.sync.aligned.m16n8k16.row.col.f32.bf16.bf16.f32 " \
        "{%0,%1,%2,%3}, {%4,%5,%6,%7}, {%8,%9}, {%0,%1,%2,%3};" \
        : "+f"((d)[0]), "+f"((d)[1]), "+f"((d)[2]), "+f"((d)[3]) \
        : "r"((a)[0]), "r"((a)[1]), "r"((a)[2]), "r"((a)[3]), \
          "r"((b)[0]), "r"((b)[1]))

enum { E_NONE = 0, E_BROW = 1, E_RES = 2, E_BN = 3, E_BNRES = 4 };

// ===========================================================================
// split-plane fp32 -> (hi, lo) bf16 planes
// ===========================================================================
__global__ __launch_bounds__(256) void k_cvt(const float* __restrict__ X,
                                             bf16* __restrict__ H,
                                             bf16* __restrict__ L, int n4)
{
    const int i = blockIdx.x * 256 + threadIdx.x;
    if (i >= n4) return;
    float4 v = *(const float4*)(X + (size_t)i * 4);
    bf16 h0,l0,h1,l1,h2,l2,h3,l3;
    spl(v.x,h0,l0); spl(v.y,h1,l1); spl(v.z,h2,l2); spl(v.w,h3,l3);
    *(uint2*)(H + (size_t)i * 4) = make_uint2(pk(h0,h1), pk(h2,h3));
    *(uint2*)(L + (size_t)i * 4) = make_uint2(pk(l0,l1), pk(l2,l3));
}

// ===========================================================================
// HMMA GEMM, 3-stage cp.async pipeline: D[m][n] = sum_k A[m][k]*B[k][n]
// tile 128x64x32, 8 warps (4x2), warp tile 32x32, 2 CTAs/SM.
// ===========================================================================
template <int EPI, bool TA, bool I2C, bool OF32, bool OBF>
__global__ __launch_bounds__(256, 2) void k_mm(
    const bf16* __restrict__ Ah, const bf16* __restrict__ Al,
    size_t Abs, int lda,
    const bf16* __restrict__ Bh, const bf16* __restrict__ Bl,
    size_t Bbs, int ldb, int Ktot,
    float* __restrict__ D, bf16* __restrict__ Dh, bf16* __restrict__ Dl,
    size_t Dbs, int ldd,
    const float* __restrict__ bias,
    const float* __restrict__ Res, size_t Rbs,
    const float* __restrict__ bns, const float* __restrict__ bnb,
    const float* __restrict__ bnm, const float* __restrict__ bnv)
{
    extern __shared__ char sm[];
    constexpr int ASZ = TA ? (BKT * AM_PAD * 2) : (BMT * AK_PAD * 2);
    constexpr int BSZ = BKT * BN_PAD * 2;
    constexpr int STG = 2 * ASZ + 2 * BSZ;

    const int tid = threadIdx.x, wid = tid >> 5, lane = tid & 31;
    const int wm = wid & 3, wn = wid >> 2;
    const int colT = blockIdx.x * BNT, rowT = blockIdx.y * BMT, bz = blockIdx.z;
    const uint32_t su = smem_u32(sm);

    const bf16* Ah_b = Ah + (size_t)bz * Abs;
    const bf16* Al_b = Al + (size_t)bz * Abs;
    const bf16* Bh_b = Bh + (size_t)bz * Bbs;
    const bf16* Bl_b = Bl + (size_t)bz * Bbs;

    float acc[2][4][4];
    #pragma unroll
    for (int i = 0; i < 2; i++)
        #pragma unroll
        for (int j = 0; j < 4; j++)
            #pragma unroll
            for (int q = 0; q < 4; q++) acc[i][j][q] = 0.f;

    auto cpa = [&](int k0, int s) {
        const uint32_t base = su + s * STG;
        if constexpr (!TA) {
            #pragma unroll
            for (int i = 0; i < 2; i++) {
                const int idx = tid + (i << 8);
                const int row = idx >> 2, c4 = idx & 3;
                const size_t so = (size_t)(rowT + row) * lda + k0 + c4 * 8;
                const uint32_t d = base + (uint32_t)row * (AK_PAD * 2) + c4 * 16;
                CPA(d, Ah_b + so);
                CPA(d + ASZ, Al_b + so);
            }
        } else {
            #pragma unroll
            for (int i = 0; i < 2; i++) {
                const int idx = tid + (i << 8);
                const int row = idx >> 4, c16 = idx & 15;
                const size_t so = (size_t)(k0 + row) * lda + rowT + c16 * 8;
                const uint32_t d = base + (uint32_t)row * (AM_PAD * 2) + c16 * 16;
                CPA(d, Ah_b + so);
                CPA(d + ASZ, Al_b + so);
            }
        }
        if constexpr (!I2C) {
            const int row = tid >> 3, c8 = tid & 7;
            const size_t so = (size_t)(k0 + row) * ldb + colT + c8 * 8;
            const uint32_t d = base + 2 * ASZ + (uint32_t)row * (BN_PAD * 2) + c8 * 16;
            CPA(d, Bh_b + so);
            CPA(d + BSZ, Bl_b + so);
        }
    };

    unsigned short bh_[8], bl_[8];
    auto ldB_i2c = [&](int k0) {
        const unsigned short* BhU = (const unsigned short*)Bh_b;
        const unsigned short* BlU = (const unsigned short*)Bl_b;
        #pragma unroll
        for (int j = 0; j < 2; j++) {
            const int kg = k0 + (tid >> 4) + j * 16;
            const int c  = kg / 9;
            const int r  = kg - c * 9;
            const int ky = r / 3;
            const int kx = r - ky * 3;
            const size_t cb = (size_t)c * NPIX;
            #pragma unroll
            for (int u = 0; u < 4; u++) {
                const int p = colT + ((tid & 15) << 2) + u;
                const int y = p / WWW, x = p - y * WWW;
                const int sy = y + ky - 1, sx = x + kx - 1;
                const bool ok = (unsigned)sy < (unsigned)HHH &&
                                (unsigned)sx < (unsigned)WWW;
                const size_t off = cb + sy * WWW + sx;
                bh_[j * 4 + u] = ok ? BhU[off] : 0;
                bl_[j * 4 + u] = ok ? BlU[off] : 0;
            }
        }
    };
    auto stsB_i2c = [&](int s) {
        char* hi = sm + s * STG + 2 * ASZ;
        char* lo = hi + BSZ;
        #pragma unroll
        for (int j = 0; j < 2; j++) {
            const uint32_t off = (uint32_t)((tid >> 4) + j * 16) * (BN_PAD * 2)
                                 + ((tid & 15) << 3);
            *(uint2*)(hi + off) = make_uint2(
                (uint32_t)bh_[j*4+0] | ((uint32_t)bh_[j*4+1] << 16),
                (uint32_t)bh_[j*4+2] | ((uint32_t)bh_[j*4+3] << 16));
            *(uint2*)(lo + off) = make_uint2(
                (uint32_t)bl_[j*4+0] | ((uint32_t)bl_[j*4+1] << 16),
                (uint32_t)bl_[j*4+2] | ((uint32_t)bl_[j*4+3] << 16));
        }
    };

    const int mtx = lane >> 3, r8 = lane & 7;
    uint32_t aoff[2][2];
    #pragma unroll
    for (int mi = 0; mi < 2; mi++)
        #pragma unroll
        for (int ks = 0; ks < 2; ks++) {
            if constexpr (!TA) {
                const int row = wm * 32 + mi * 16 + (mtx & 1) * 8 + r8;
                const int kc  = ks * 16 + (mtx >> 1) * 8;
                aoff[mi][ks] = (uint32_t)row * (AK_PAD * 2) + kc * 2;
            } else {
                const int kk = ks * 16 + (mtx >> 1) * 8 + r8;
                const int mm = wm * 32 + mi * 16 + (mtx & 1) * 8;
                aoff[mi][ks] = (uint32_t)kk * (AM_PAD * 2) + mm * 2;
            }
        }
    uint32_t boff[2][2];
    #pragma unroll
    for (int ni2 = 0; ni2 < 2; ni2++)
        #pragma unroll
        for (int ks = 0; ks < 2; ks++) {
            const int kb = ks * 16 + (mtx & 1) * 8 + r8;
            const int nb = wn * 32 + ni2 * 16 + (mtx >> 1) * 8;
            boff[ni2][ks] = (uint32_t)kb * (BN_PAD * 2) + nb * 2;
        }

    const int nch = Ktot / BKT;

    // prologue: stages 0 and 1 in flight
    cpa(0, 0);
    CPA_COMMIT();
    if (nch > 1) { cpa(BKT, 1); CPA_COMMIT(); }
    if constexpr (I2C) { ldB_i2c(0); stsB_i2c(0); }

    int s = 0;
    for (int i = 0; i < nch; i++) {
        if (i + 1 < nch) CPA_WAIT1(); else CPA_WAIT0();
        __syncthreads();
        if (i + 2 < nch) {
            int s2 = s + 2; if (s2 >= 3) s2 -= 3;
            cpa((i + 2) * BKT, s2);
            CPA_COMMIT();
        }
        if constexpr (I2C) { if (i + 1 < nch) ldB_i2c((i + 1) * BKT); }

        const uint32_t aHi = su + s * STG;
        const uint32_t aLo = aHi + ASZ;
        const uint32_t bHi = aHi + 2 * ASZ;
        const uint32_t bLo = bHi + BSZ;

        #pragma unroll
        for (int ks = 0; ks < 2; ks++) {
            uint32_t ah[2][4], al[2][4];
            #pragma unroll
            for (int mi = 0; mi < 2; mi++) {
                if constexpr (!TA) {
                    LDMX4(ah[mi], aHi + aoff[mi][ks]);
                    LDMX4(al[mi], aLo + aoff[mi][ks]);
                } else {
                    LDMX4T(ah[mi], aHi + aoff[mi][ks]);
                    LDMX4T(al[mi], aLo + aoff[mi][ks]);
                }
            }
            #pragma unroll
            for (int ni2 = 0; ni2 < 2; ni2++) {
                uint32_t bh[4], bl[4];
                LDMX4T(bh, bHi + boff[ni2][ks]);
                LDMX4T(bl, bLo + boff[ni2][ks]);
                #pragma unroll
                for (int mi = 0; mi < 2; mi++) {
                    #pragma unroll
                    for (int nf = 0; nf < 2; nf++) {
                        float* ac = acc[mi][ni2 * 2 + nf];
                        MMA16816(ac, ah[mi], bh + nf * 2);
                        MMA16816(ac, ah[mi], bl + nf * 2);
                        MMA16816(ac, al[mi], bh + nf * 2);
                    }
                }
            }
        }
        if constexpr (I2C) {
            if (i + 1 < nch) {
                int s1 = s + 1; if (s1 >= 3) s1 -= 3;
                stsB_i2c(s1);
            }
        }
        s += 1; if (s >= 3) s = 0;
    }

    // ---- epilogue ----
    #pragma unroll
    for (int mi = 0; mi < 2; mi++) {
        const int r = rowT + wm * 32 + mi * 16 + (lane >> 2);
        float ba = 0.f, bb_ = 0.f, inva = 0.f, beta_a = 0.f, invb = 0.f, beta_b = 0.f;
        if (EPI == E_BROW) { ba = bias[r]; bb_ = bias[r + 8]; }
        if (EPI == E_BN || EPI == E_BNRES) {
            inva = bns[r] * rsqrtf(bnv[r] + EPSB);
            beta_a = bnb[r] - bnm[r] * inva;
            invb = bns[r + 8] * rsqrtf(bnv[r + 8] + EPSB);
            beta_b = bnb[r + 8] - bnm[r + 8] * invb;
        }
        const size_t ro0 = (size_t)bz * Dbs + (size_t)r * ldd;
        const size_t ro1 = ro0 + 8 * (size_t)ldd;
        const float* rs0 = (EPI == E_RES || EPI == E_BNRES)
                               ? Res + (size_t)bz * Rbs + (size_t)r * ldd : nullptr;
        const float* rs1 = rs0 ? rs0 + 8 * (size_t)ldd : nullptr;
        #pragma unroll
        for (int ni = 0; ni < 4; ni++) {
            const int c = colT + wn * 32 + ni * 8 + ((lane & 3) << 1);
            float v0 = acc[mi][ni][0], v1 = acc[mi][ni][1];
            float v2 = acc[mi][ni][2], v3 = acc[mi][ni][3];
            if (EPI == E_BROW) {
                v0 += ba; v1 += ba; v2 += bb_; v3 += bb_;
            } else if (EPI == E_RES) {
                float2 f0 = *(const float2*)(rs0 + c);
                float2 f1 = *(const float2*)(rs1 + c);
                v0 += f0.x; v1 += f0.y; v2 += f1.x; v3 += f1.y;
            } else if (EPI == E_BN) {
                v0 = fmaxf(v0 * inva + beta_a, 0.f);
                v1 = fmaxf(v1 * inva + beta_a, 0.f);
                v2 = fmaxf(v2 * invb + beta_b, 0.f);
                v3 = fmaxf(v3 * invb + beta_b, 0.f);
            } else if (EPI == E_BNRES) {
                float2 f0 = *(const float2*)(rs0 + c);
                float2 f1 = *(const float2*)(rs1 + c);
                v0 = fmaxf(v0 * inva + beta_a + f0.x, 0.f) + f0.x;
                v1 = fmaxf(v1 * inva + beta_a + f0.y, 0.f) + f0.y;
                v2 = fmaxf(v2 * invb + beta_b + f1.x, 0.f) + f1.x;
                v3 = fmaxf(v3 * invb + beta_b + f1.y, 0.f) + f1.y;
            }
            if (OF32) {
                *(float2*)(D + ro0 + c) = make_float2(v0, v1);
                *(float2*)(D + ro1 + c) = make_float2(v2, v3);
            }
            if (OBF) {
                wr_bf(Dh, Dl, ro0 + c, v0, v1);
                wr_bf(Dh, Dl, ro1 + c, v2, v3);
            }
        }
    }
}

// ===========================================================================
// Row softmax; reads fp32 scores, writes split-bf16 attn planes
// ===========================================================================
__global__ __launch_bounds__(256) void k_softmax(const float* __restrict__ S,
                                                 bf16* __restrict__ Ah,
                                                 bf16* __restrict__ Al)
{
    const size_t base = (size_t)blockIdx.x * NPIX;
    const float* p = S + base;
    const int tid = threadIdx.x;
    float v[9];
    float mx = -1e30f;
    #pragma unroll
    for (int i = 0; i < 9; i++) {
        v[i] = p[tid + (i << 8)];
        mx = fmaxf(mx, v[i]);
    }
    __shared__ float red[8];
    #pragma unroll
    for (int o = 16; o > 0; o >>= 1)
        mx = fmaxf(mx, __shfl_xor_sync(0xffffffffu, mx, o));
    if ((tid & 31) == 0) red[tid >> 5] = mx;
    __syncthreads();
    float m2 = red[0];
    #pragma unroll
    for (int i = 1; i < 8; i++) m2 = fmaxf(m2, red[i]);
    __syncthreads();
    float s = 0.f;
    #pragma unroll
    for (int i = 0; i < 9; i++) { v[i] = __expf(v[i] - m2); s += v[i]; }
    #pragma unroll
    for (int o = 16; o > 0; o >>= 1)
        s += __shfl_xor_sync(0xffffffffu, s, o);
    if ((tid & 31) == 0) red[tid >> 5] = s;
    __syncthreads();
    float s2 = 0.f;
    #pragma unroll
    for (int i = 0; i < 8; i++) s2 += red[i];
    const float inv = 1.0f / s2;
    #pragma unroll
    for (int i = 0; i < 9; i++) {
        bf16 h, l;
        spl(v[i] * inv, h, l);
        Ah[base + tid + (i << 8)] = h;
        Al[base + tid + (i << 8)] = l;
    }
}

// ===========================================================================
// Host launcher
// ===========================================================================
extern "C" void kernel_launch(void* const* d_in, const int* in_sizes, int n_in,
                              void* d_out, int out_size)
{
    (void)in_sizes; (void)n_in; (void)out_size;
    const float* F_b  = (const float*)d_in[0];
    const float* F_a  = (const float*)d_in[1];
    const float* qw   = (const float*)d_in[2];
    const float* qb   = (const float*)d_in[3];
    const float* kw   = (const float*)d_in[4];
    const float* kb   = (const float*)d_in[5];
    const float* vw   = (const float*)d_in[6];
    const float* vb   = (const float*)d_in[7];
    const float* c1w  = (const float*)d_in[8];
    const float* bn1s = (const float*)d_in[9];
    const float* bn1b = (const float*)d_in[10];
    const float* bn1m = (const float*)d_in[11];
    const float* bn1v = (const float*)d_in[12];
    const float* c2w  = (const float*)d_in[13];
    const float* bn2s = (const float*)d_in[14];
    const float* bn2b = (const float*)d_in[15];
    const float* bn2m = (const float*)d_in[16];
    const float* bn2v = (const float*)d_in[17];
    float* out = (float*)d_out;

    float *scores, *fused;
    bf16 *Fbh,*Fbl,*Fah,*Fal,*qwh,*qwl,*kwh,*kwl,*vwh,*vwl;
    bf16 *c1h,*c1l,*c2h,*c2l,*Qh,*Ql,*Kh,*Kl,*Vh,*Vl;
    bf16 *Ath,*Atl,*Fh,*Fl,*th,*tl;
    cudaGetSymbolAddress((void**)&scores, g_scores);
    cudaGetSymbolAddress((void**)&fused,  g_fused);
    cudaGetSymbolAddress((void**)&Fbh, g_Fbh); cudaGetSymbolAddress((void**)&Fbl, g_Fbl);
    cudaGetSymbolAddress((void**)&Fah, g_Fah); cudaGetSymbolAddress((void**)&Fal, g_Fal);
    cudaGetSymbolAddress((void**)&qwh, g_qwh); cudaGetSymbolAddress((void**)&qwl, g_qwl);
    cudaGetSymbolAddress((void**)&kwh, g_kwh); cudaGetSymbolAddress((void**)&kwl, g_kwl);
    cudaGetSymbolAddress((void**)&vwh, g_vwh); cudaGetSymbolAddress((void**)&vwl, g_vwl);
    cudaGetSymbolAddress((void**)&c1h, g_c1h); cudaGetSymbolAddress((void**)&c1l, g_c1l);
    cudaGetSymbolAddress((void**)&c2h, g_c2h); cudaGetSymbolAddress((void**)&c2l, g_c2l);
    cudaGetSymbolAddress((void**)&Qh,  g_Qh);  cudaGetSymbolAddress((void**)&Ql,  g_Ql);
    cudaGetSymbolAddress((void**)&Kh,  g_Kh);  cudaGetSymbolAddress((void**)&Kl,  g_Kl);
    cudaGetSymbolAddress((void**)&Vh,  g_Vh);  cudaGetSymbolAddress((void**)&Vl,  g_Vl);
    cudaGetSymbolAddress((void**)&Ath, g_Ath); cudaGetSymbolAddress((void**)&Atl, g_Atl);
    cudaGetSymbolAddress((void**)&Fh,  g_Fh);  cudaGetSymbolAddress((void**)&Fl,  g_Fl);
    cudaGetSymbolAddress((void**)&th,  g_th);  cudaGetSymbolAddress((void**)&tl,  g_tl);

    const int STG_MK = 2 * (BMT * AK_PAD * 2) + 2 * (BKT * BN_PAD * 2); // 29696
    const int STG_KM = 2 * (BKT * AM_PAD * 2) + 2 * (BKT * BN_PAD * 2); // 26624
    const int SMEM_MK = 3 * STG_MK;   // 89088
    const int SMEM_KM = 3 * STG_KM;   // 79872

    cudaFuncSetAttribute((const void*)k_mm<E_BROW,  false, false, false, true >, cudaFuncAttributeMaxDynamicSharedMemorySize, SMEM_MK);
    cudaFuncSetAttribute((const void*)k_mm<E_NONE,  true,  false, true,  false>, cudaFuncAttributeMaxDynamicSharedMemorySize, SMEM_KM);
    cudaFuncSetAttribute((const void*)k_mm<E_RES,   false, false, true,  true >, cudaFuncAttributeMaxDynamicSharedMemorySize, SMEM_MK);
    cudaFuncSetAttribute((const void*)k_mm<E_BN,    false, true,  false, true >, cudaFuncAttributeMaxDynamicSharedMemorySize, SMEM_MK);
    cudaFuncSetAttribute((const void*)k_mm<E_BNRES, false, true,  true,  false>, cudaFuncAttributeMaxDynamicSharedMemorySize, SMEM_MK);

    dim3 blk(256);
    dim3 gFeat(NPIX / BNT, CCH / BMT, BBATCH);   // (36, 2, 16)
    dim3 gScor(NPIX / BNT, NPIX / BMT, BBATCH);  // (36, 18, 16)
    const size_t FS = (size_t)CCH * NPIX;
    const size_t AS = (size_t)NPIX * NPIX;

    // ---- preconvert inputs/weights to split-bf16 planes ----
    k_cvt<<<(int)(FSZ/4/256), blk>>>(F_b, Fbh, Fbl, (int)(FSZ/4));
    k_cvt<<<(int)(FSZ/4/256), blk>>>(F_a, Fah, Fal, (int)(FSZ/4));
    k_cvt<<<CCH*CCH/4/256, blk>>>(qw, qwh, qwl, CCH*CCH/4);
    k_cvt<<<CCH*CCH/4/256, blk>>>(kw, kwh, kwl, CCH*CCH/4);
    k_cvt<<<CCH*CCH/4/256, blk>>>(vw, vwh, vwl, CCH*CCH/4);
    k_cvt<<<CCH*KCONV/4/256, blk>>>(c1w, c1h, c1l, CCH*KCONV/4);
    k_cvt<<<CCH*KCONV/4/256, blk>>>(c2w, c2h, c2l, CCH*KCONV/4);

    // ---- Q, K, V ----
    k_mm<E_BROW, false, false, false, true><<<gFeat, blk, SMEM_MK>>>(
        qwh, qwl, 0, CCH, Fbh, Fbl, FS, NPIX, CCH,
        nullptr, Qh, Ql, FS, NPIX, qb, nullptr, 0,
        nullptr, nullptr, nullptr, nullptr);
    k_mm<E_BROW, false, false, false, true><<<gFeat, blk, SMEM_MK>>>(
        kwh, kwl, 0, CCH, Fah, Fal, FS, NPIX, CCH,
        nullptr, Kh, Kl, FS, NPIX, kb, nullptr, 0,
        nullptr, nullptr, nullptr, nullptr);
    k_mm<E_BROW, false, false, false, true><<<gFeat, blk, SMEM_MK>>>(
        vwh, vwl, 0, CCH, Fah, Fal, FS, NPIX, CCH,
        nullptr, Vh, Vl, FS, NPIX, vb, nullptr, 0,
        nullptr, nullptr, nullptr, nullptr);

    // ---- scores[n][m] = sum_c K[c][n] * Q[c][m] (fp32 out) ----
    k_mm<E_NONE, true, false, true, false><<<gScor, blk, SMEM_KM>>>(
        Kh, Kl, FS, NPIX, Qh, Ql, FS, NPIX, CCH,
        scores, nullptr, nullptr, AS, NPIX, nullptr, nullptr, 0,
        nullptr, nullptr, nullptr, nullptr);

    // ---- softmax -> split-bf16 attn ----
    k_softmax<<<BBATCH * NPIX, blk>>>(scores, Ath, Atl);

    // ---- fused = V @ attn + F_b (fp32 + planes) ----
    k_mm<E_RES, false, false, true, true><<<gFeat, blk, SMEM_MK>>>(
        Vh, Vl, FS, NPIX, Ath, Atl, AS, NPIX, NPIX,
        fused, Fh, Fl, FS, NPIX, nullptr, F_b, FS,
        nullptr, nullptr, nullptr, nullptr);

    // ---- conv1 + bn1 + relu -> tmp planes ----
    k_mm<E_BN, false, true, false, true><<<gFeat, blk, SMEM_MK>>>(
        c1h, c1l, 0, KCONV, Fh, Fl, FS, 0, KCONV,
        nullptr, th, tl, FS, NPIX, nullptr, nullptr, 0,
        bn1s, bn1b, bn1m, bn1v);
    // ---- conv2 + bn2 + residual -> out ----
    k_mm<E_BNRES, false, true, true, false><<<gFeat, blk, SMEM_MK>>>(
        c2h, c2l, 0, KCONV, th, tl, FS, 0, KCONV,
        out, nullptr, nullptr, FS, NPIX, nullptr, fused, FS,
        bn2s, bn2b, bn2m, bn2v);
}

// round 10
// speedup vs baseline: 1.0944x; 1.0944x over previous
#include <cuda_runtime.h>
#include <cuda_bf16.h>
#include <cstdint>

#define BBATCH 16
#define CCH    256
#define HHH    48
#define WWW    48
#define NPIX   2304
#define KCONV  2304
#define EPSB   1e-5f

#define BMT 128
#define BNT 64
#define BKT 32

#define AK_PAD 40     // bf16 A [m][k] rows: 40 bf16 = 80B
#define AM_PAD 136    // bf16 A [k][m] rows (TA): 272B
#define BN_PAD 72     // bf16 B [k][n] rows: 144B

typedef __nv_bfloat16 bf16;

// ---------------- scratch ----------------
#define FSZ  ((size_t)BBATCH * CCH * NPIX)
#define ASZG ((size_t)BBATCH * NPIX * NPIX)

__device__ float g_scores[ASZG];
__device__ float g_fused [FSZ];          // exact fp32 (residual)
__device__ float g_ft32  [FSZ];          // tf32-rounded fused (conv1 input)
__device__ float g_tt32  [FSZ];          // tf32-rounded tmp   (conv2 input)
__device__ float g_c1t   [CCH*KCONV];    // tf32-rounded conv weights
__device__ float g_c2t   [CCH*KCONV];

__device__ __align__(16) bf16 g_Fbh[FSZ], g_Fbl[FSZ], g_Fah[FSZ], g_Fal[FSZ];
__device__ __align__(16) bf16 g_qwh[CCH*CCH], g_qwl[CCH*CCH];
__device__ __align__(16) bf16 g_kwh[CCH*CCH], g_kwl[CCH*CCH];
__device__ __align__(16) bf16 g_vwh[CCH*CCH], g_vwl[CCH*CCH];
__device__ __align__(16) bf16 g_Qh[FSZ], g_Ql[FSZ], g_Kh[FSZ], g_Kl[FSZ];
__device__ __align__(16) bf16 g_Vh[FSZ], g_Vl[FSZ];
__device__ __align__(16) bf16 g_Ath[ASZG], g_Atl[ASZG];

// ---------------- helpers ----------------
__device__ __forceinline__ uint32_t smem_u32(const void* p) {
    uint32_t a;
    asm("{ .reg .u64 t; cvta.to.shared.u64 t, %1; cvt.u32.u64 %0, t; }"
        : "=r"(a) : "l"(p));
    return a;
}
__device__ __forceinline__ uint32_t pk(bf16 a, bf16 b) {
    return (uint32_t)__bfloat16_as_ushort(a) |
           ((uint32_t)__bfloat16_as_ushort(b) << 16);
}
__device__ __forceinline__ void spl(float x, bf16& h, bf16& l) {
    h = __float2bfloat16(x);
    l = __float2bfloat16(x - __bfloat162float(h));
}
__device__ __forceinline__ void wr_bf(bf16* H, bf16* L, size_t off,
                                      float a, float b) {
    bf16 h0, l0, h1, l1;
    spl(a, h0, l0); spl(b, h1, l1);
    *(uint32_t*)(H + off) = pk(h0, h1);
    *(uint32_t*)(L + off) = pk(l0, l1);
}
__device__ __forceinline__ float rna32(float x) {
    uint32_t u;
    asm("cvt.rna.tf32.f32 %0, %1;" : "=r"(u) : "f"(x));
    return __uint_as_float(u);
}

#define CPA(d, s)     asm volatile("cp.async.cg.shared.global [%0], [%1], 16;" :: "r"(d), "l"(s))
#define CPA_COMMIT()  asm volatile("cp.async.commit_group;")
#define CPA_WAIT0()   asm volatile("cp.async.wait_group 0;")
#define CPA_WAIT1()   asm volatile("cp.async.wait_group 1;")

#define LDMX4(R, addr) \
    asm volatile("ldmatrix.sync.aligned.m8n8.x4.shared.b16 {%0,%1,%2,%3}, [%4];" \
        : "=r"((R)[0]), "=r"((R)[1]), "=r"((R)[2]), "=r"((R)[3]) : "r"(addr))
#define LDMX4T(R, addr) \
    asm volatile("ldmatrix.sync.aligned.m8n8.x4.trans.shared.b16 {%0,%1,%2,%3}, [%4];" \
        : "=r"((R)[0]), "=r"((R)[1]), "=r"((R)[2]), "=r"((R)[3]) : "r"(addr))
#define MMA16816(d, a, b) \
    asm volatile("mma.sync.aligned.m16n8k16.row.col.f32.bf16.bf16.f32 " \
        "{%0,%1,%2,%3}, {%4,%5,%6,%7}, {%8,%9}, {%0,%1,%2,%3};" \
        : "+f"((d)[0]), "+f"((d)[1]), "+f"((d)[2]), "+f"((d)[3]) \
        : "r"((a)[0]), "r"((a)[1]), "r"((a)[2]), "r"((a)[3]), \
          "r"((b)[0]), "r"((b)[1]))
#define MMATF32(d, a, b) \
    asm volatile("mma.sync.aligned.m16n8k8.row.col.f32.tf32.tf32.f32 " \
        "{%0,%1,%2,%3}, {%4,%5,%6,%7}, {%8,%9}, {%0,%1,%2,%3};" \
        : "+f"((d)[0]), "+f"((d)[1]), "+f"((d)[2]), "+f"((d)[3]) \
        : "r"((a)[0]), "r"((a)[1]), "r"((a)[2]), "r"((a)[3]), \
          "r"((b)[0]), "r"((b)[1]))

enum { E_NONE = 0, E_BROW = 1, E_RES = 2 };

// ===========================================================================
// converters
// ===========================================================================
__global__ __launch_bounds__(256) void k_cvt(const float* __restrict__ X,
                                             bf16* __restrict__ H,
                                             bf16* __restrict__ L, int n4)
{
    const int i = blockIdx.x * 256 + threadIdx.x;
    if (i >= n4) return;
    float4 v = *(const float4*)(X + (size_t)i * 4);
    bf16 h0,l0,h1,l1,h2,l2,h3,l3;
    spl(v.x,h0,l0); spl(v.y,h1,l1); spl(v.z,h2,l2); spl(v.w,h3,l3);
    *(uint2*)(H + (size_t)i * 4) = make_uint2(pk(h0,h1), pk(h2,h3));
    *(uint2*)(L + (size_t)i * 4) = make_uint2(pk(l0,l1), pk(l2,l3));
}
__global__ __launch_bounds__(256) void k_cvt32(const float* __restrict__ X,
                                               float* __restrict__ T, int n4)
{
    const int i = blockIdx.x * 256 + threadIdx.x;
    if (i >= n4) return;
    float4 v = *(const float4*)(X + (size_t)i * 4);
    v.x = rna32(v.x); v.y = rna32(v.y); v.z = rna32(v.z); v.w = rna32(v.w);
    *(float4*)(T + (size_t)i * 4) = v;
}

// ===========================================================================
// bf16 split HMMA GEMM (attention path), 3-stage cp.async (unchanged R8 core)
// ===========================================================================
template <int EPI, bool TA, bool OF32, bool OBF, bool OT32>
__global__ __launch_bounds__(256, 2) void k_mm(
    const bf16* __restrict__ Ah, const bf16* __restrict__ Al,
    size_t Abs, int lda,
    const bf16* __restrict__ Bh, const bf16* __restrict__ Bl,
    size_t Bbs, int ldb, int Ktot,
    float* __restrict__ D, bf16* __restrict__ Dh, bf16* __restrict__ Dl,
    float* __restrict__ Dt,
    size_t Dbs, int ldd,
    const float* __restrict__ bias,
    const float* __restrict__ Res, size_t Rbs)
{
    extern __shared__ char sm[];
    constexpr int ASZ = TA ? (BKT * AM_PAD * 2) : (BMT * AK_PAD * 2);
    constexpr int BSZ = BKT * BN_PAD * 2;
    constexpr int STG = 2 * ASZ + 2 * BSZ;

    const int tid = threadIdx.x, wid = tid >> 5, lane = tid & 31;
    const int wm = wid & 3, wn = wid >> 2;
    const int colT = blockIdx.x * BNT, rowT = blockIdx.y * BMT, bz = blockIdx.z;
    const uint32_t su = smem_u32(sm);

    const bf16* Ah_b = Ah + (size_t)bz * Abs;
    const bf16* Al_b = Al + (size_t)bz * Abs;
    const bf16* Bh_b = Bh + (size_t)bz * Bbs;
    const bf16* Bl_b = Bl + (size_t)bz * Bbs;

    float acc[2][4][4];
    #pragma unroll
    for (int i = 0; i < 2; i++)
        #pragma unroll
        for (int j = 0; j < 4; j++)
            #pragma unroll
            for (int q = 0; q < 4; q++) acc[i][j][q] = 0.f;

    auto cpa = [&](int k0, int s) {
        const uint32_t base = su + s * STG;
        if constexpr (!TA) {
            #pragma unroll
            for (int i = 0; i < 2; i++) {
                const int idx = tid + (i << 8);
                const int row = idx >> 2, c4 = idx & 3;
                const size_t so = (size_t)(rowT + row) * lda + k0 + c4 * 8;
                const uint32_t d = base + (uint32_t)row * (AK_PAD * 2) + c4 * 16;
                CPA(d, Ah_b + so);
                CPA(d + ASZ, Al_b + so);
            }
        } else {
            #pragma unroll
            for (int i = 0; i < 2; i++) {
                const int idx = tid + (i << 8);
                const int row = idx >> 4, c16 = idx & 15;
                const size_t so = (size_t)(k0 + row) * lda + rowT + c16 * 8;
                const uint32_t d = base + (uint32_t)row * (AM_PAD * 2) + c16 * 16;
                CPA(d, Ah_b + so);
                CPA(d + ASZ, Al_b + so);
            }
        }
        const int row = tid >> 3, c8 = tid & 7;
        const size_t so = (size_t)(k0 + row) * ldb + colT + c8 * 8;
        const uint32_t d = base + 2 * ASZ + (uint32_t)row * (BN_PAD * 2) + c8 * 16;
        CPA(d, Bh_b + so);
        CPA(d + BSZ, Bl_b + so);
    };

    const int mtx = lane >> 3, r8 = lane & 7;
    uint32_t aoff[2][2];
    #pragma unroll
    for (int mi = 0; mi < 2; mi++)
        #pragma unroll
        for (int ks = 0; ks < 2; ks++) {
            if constexpr (!TA) {
                const int row = wm * 32 + mi * 16 + (mtx & 1) * 8 + r8;
                const int kc  = ks * 16 + (mtx >> 1) * 8;
                aoff[mi][ks] = (uint32_t)row * (AK_PAD * 2) + kc * 2;
            } else {
                const int kk = ks * 16 + (mtx >> 1) * 8 + r8;
                const int mm = wm * 32 + mi * 16 + (mtx & 1) * 8;
                aoff[mi][ks] = (uint32_t)kk * (AM_PAD * 2) + mm * 2;
            }
        }
    uint32_t boff[2][2];
    #pragma unroll
    for (int ni2 = 0; ni2 < 2; ni2++)
        #pragma unroll
        for (int ks = 0; ks < 2; ks++) {
            const int kb = ks * 16 + (mtx & 1) * 8 + r8;
            const int nb = wn * 32 + ni2 * 16 + (mtx >> 1) * 8;
            boff[ni2][ks] = (uint32_t)kb * (BN_PAD * 2) + nb * 2;
        }

    const int nch = Ktot / BKT;
    cpa(0, 0);
    CPA_COMMIT();
    if (nch > 1) { cpa(BKT, 1); CPA_COMMIT(); }

    int s = 0;
    for (int i = 0; i < nch; i++) {
        if (i + 1 < nch) CPA_WAIT1(); else CPA_WAIT0();
        __syncthreads();
        if (i + 2 < nch) {
            int s2 = s + 2; if (s2 >= 3) s2 -= 3;
            cpa((i + 2) * BKT, s2);
            CPA_COMMIT();
        }
        const uint32_t aHi = su + s * STG;
        const uint32_t aLo = aHi + ASZ;
        const uint32_t bHi = aHi + 2 * ASZ;
        const uint32_t bLo = bHi + BSZ;

        #pragma unroll
        for (int ks = 0; ks < 2; ks++) {
            uint32_t ah[2][4], al[2][4];
            #pragma unroll
            for (int mi = 0; mi < 2; mi++) {
                if constexpr (!TA) {
                    LDMX4(ah[mi], aHi + aoff[mi][ks]);
                    LDMX4(al[mi], aLo + aoff[mi][ks]);
                } else {
                    LDMX4T(ah[mi], aHi + aoff[mi][ks]);
                    LDMX4T(al[mi], aLo + aoff[mi][ks]);
                }
            }
            #pragma unroll
            for (int ni2 = 0; ni2 < 2; ni2++) {
                uint32_t bh[4], bl[4];
                LDMX4T(bh, bHi + boff[ni2][ks]);
                LDMX4T(bl, bLo + boff[ni2][ks]);
                #pragma unroll
                for (int mi = 0; mi < 2; mi++) {
                    #pragma unroll
                    for (int nf = 0; nf < 2; nf++) {
                        float* ac = acc[mi][ni2 * 2 + nf];
                        MMA16816(ac, ah[mi], bh + nf * 2);
                        MMA16816(ac, ah[mi], bl + nf * 2);
                        MMA16816(ac, al[mi], bh + nf * 2);
                    }
                }
            }
        }
        s += 1; if (s >= 3) s = 0;
    }

    // epilogue
    #pragma unroll
    for (int mi = 0; mi < 2; mi++) {
        const int r = rowT + wm * 32 + mi * 16 + (lane >> 2);
        float ba = 0.f, bb_ = 0.f;
        if (EPI == E_BROW) { ba = bias[r]; bb_ = bias[r + 8]; }
        const size_t ro0 = (size_t)bz * Dbs + (size_t)r * ldd;
        const size_t ro1 = ro0 + 8 * (size_t)ldd;
        const float* rs0 = (EPI == E_RES)
                               ? Res + (size_t)bz * Rbs + (size_t)r * ldd : nullptr;
        const float* rs1 = rs0 ? rs0 + 8 * (size_t)ldd : nullptr;
        #pragma unroll
        for (int ni = 0; ni < 4; ni++) {
            const int c = colT + wn * 32 + ni * 8 + ((lane & 3) << 1);
            float v0 = acc[mi][ni][0], v1 = acc[mi][ni][1];
            float v2 = acc[mi][ni][2], v3 = acc[mi][ni][3];
            if (EPI == E_BROW) {
                v0 += ba; v1 += ba; v2 += bb_; v3 += bb_;
            } else if (EPI == E_RES) {
                float2 f0 = *(const float2*)(rs0 + c);
                float2 f1 = *(const float2*)(rs1 + c);
                v0 += f0.x; v1 += f0.y; v2 += f1.x; v3 += f1.y;
            }
            if (OF32) {
                *(float2*)(D + ro0 + c) = make_float2(v0, v1);
                *(float2*)(D + ro1 + c) = make_float2(v2, v3);
            }
            if (OBF) {
                wr_bf(Dh, Dl, ro0 + c, v0, v1);
                wr_bf(Dh, Dl, ro1 + c, v2, v3);
            }
            if (OT32) {
                *(float2*)(Dt + ro0 + c) = make_float2(rna32(v0), rna32(v1));
                *(float2*)(Dt + ro1 + c) = make_float2(rna32(v2), rna32(v3));
            }
        }
    }
}

// ===========================================================================
// tf32 implicit-GEMM 3x3 conv + BN epilogues.  D = conv(In) per 128x64 tile.
// A [128][36]fl pad, B [32][72]fl pad; warp 32x32; occ 2; 2-stage cp.async.
// ===========================================================================
#define ASZ32 (128 * 36 * 4)
#define BSZ32 (32 * 72 * 4)
#define STG32 (ASZ32 + BSZ32)

template <bool SECOND>
__global__ __launch_bounds__(256, 2) void k_conv32(
    const float* __restrict__ Wt,     // [256][2304] tf32-rounded
    const float* __restrict__ In,     // [b][256][2304] tf32-rounded
    const float* __restrict__ bns, const float* __restrict__ bnb,
    const float* __restrict__ bnm, const float* __restrict__ bnv,
    const float* __restrict__ Res,    // exact fused (SECOND only)
    float* __restrict__ Out)          // SECOND? exact out : rounded tmp
{
    extern __shared__ char sm[];
    const int tid = threadIdx.x, wid = tid >> 5, lane = tid & 31;
    const int wm = wid & 3, wn = wid >> 2;
    const int colT = blockIdx.x * BNT, rowT = blockIdx.y * BMT, bz = blockIdx.z;
    const uint32_t su = smem_u32(sm);
    const float* Inb = In + (size_t)bz * (size_t)CCH * NPIX;

    float acc[2][4][4];
    #pragma unroll
    for (int i = 0; i < 2; i++)
        #pragma unroll
        for (int j = 0; j < 4; j++)
            #pragma unroll
            for (int q = 0; q < 4; q++) acc[i][j][q] = 0.f;

    // A: cp.async 4 chunks of 4 floats per thread
    auto cpaA = [&](int k0, int s) {
        const uint32_t base = su + s * STG32;
        #pragma unroll
        for (int i = 0; i < 4; i++) {
            const int idx = tid + (i << 8);
            const int row = idx >> 3, c4 = idx & 7;
            const size_t so = (size_t)(rowT + row) * KCONV + k0 + c4 * 4;
            CPA(base + (uint32_t)row * 144 + c4 * 16, Wt + so);
        }
    };
    // B: im2col gather 8 floats -> regs
    float bst[8];
    auto ldB = [&](int k0) {
        #pragma unroll
        for (int j = 0; j < 2; j++) {
            const int kg = k0 + (tid >> 4) + j * 16;
            const int c  = kg / 9;
            const int r  = kg - c * 9;
            const int ky = r / 3;
            const int kx = r - ky * 3;
            const size_t cb = (size_t)c * NPIX;
            #pragma unroll
            for (int u = 0; u < 4; u++) {
                const int p = colT + ((tid & 15) << 2) + u;
                const int y = p / WWW, x = p - y * WWW;
                const int sy = y + ky - 1, sx = x + kx - 1;
                const bool ok = (unsigned)sy < (unsigned)HHH &&
                                (unsigned)sx < (unsigned)WWW;
                bst[j * 4 + u] = ok ? Inb[cb + sy * WWW + sx] : 0.f;
            }
        }
    };
    auto stsB = [&](int s) {
        const uint32_t base = su + s * STG32 + ASZ32;
        #pragma unroll
        for (int j = 0; j < 2; j++) {
            const uint32_t d = base + (uint32_t)((tid >> 4) + j * 16) * 288
                               + ((tid & 15) << 4);
            asm volatile("st.shared.v4.b32 [%0], {%1,%2,%3,%4};"
                :: "r"(d), "r"(__float_as_uint(bst[j*4+0])),
                   "r"(__float_as_uint(bst[j*4+1])),
                   "r"(__float_as_uint(bst[j*4+2])),
                   "r"(__float_as_uint(bst[j*4+3])) : "memory");
        }
    };

    // fragment base offsets (bytes)
    const int gr = lane >> 2, tg = lane & 3;
    uint32_t a0off[2];
    #pragma unroll
    for (int mi = 0; mi < 2; mi++)
        a0off[mi] = (uint32_t)(wm * 32 + mi * 16 + gr) * 144 + tg * 4;
    uint32_t b0off[4];
    #pragma unroll
    for (int ni = 0; ni < 4; ni++)
        b0off[ni] = ASZ32 + (uint32_t)tg * 288
                    + (uint32_t)(wn * 32 + ni * 8 + gr) * 4;

    const int nch = KCONV / BKT;   // 72
    cpaA(0, 0);
    CPA_COMMIT();
    ldB(0); stsB(0);
    CPA_WAIT0();
    __syncthreads();

    for (int i = 0; i < nch; i++) {
        const int s = i & 1;
        if (i + 1 < nch) {
            cpaA((i + 1) * BKT, s ^ 1);
            CPA_COMMIT();
            ldB((i + 1) * BKT);
        }
        const uint32_t base = su + s * STG32;
        #pragma unroll
        for (int ks = 0; ks < 4; ks++) {
            uint32_t a[2][4], b[4][2];
            #pragma unroll
            for (int mi = 0; mi < 2; mi++) {
                const uint32_t a0 = base + a0off[mi] + ks * 32;
                asm volatile("ld.shared.b32 %0, [%1];" : "=r"(a[mi][0]) : "r"(a0));
                asm volatile("ld.shared.b32 %0, [%1];" : "=r"(a[mi][1]) : "r"(a0 + 8*144));
                asm volatile("ld.shared.b32 %0, [%1];" : "=r"(a[mi][2]) : "r"(a0 + 16));
                asm volatile("ld.shared.b32 %0, [%1];" : "=r"(a[mi][3]) : "r"(a0 + 8*144 + 16));
            }
            #pragma unroll
            for (int ni = 0; ni < 4; ni++) {
                const uint32_t b0 = base + b0off[ni] + ks * 2304;
                asm volatile("ld.shared.b32 %0, [%1];" : "=r"(b[ni][0]) : "r"(b0));
                asm volatile("ld.shared.b32 %0, [%1];" : "=r"(b[ni][1]) : "r"(b0 + 4*288));
            }
            #pragma unroll
            for (int mi = 0; mi < 2; mi++)
                #pragma unroll
                for (int ni = 0; ni < 4; ni++)
                    MMATF32(acc[mi][ni], a[mi], b[ni]);
        }
        if (i + 1 < nch) { stsB(s ^ 1); CPA_WAIT0(); }
        __syncthreads();
    }

    // epilogue
    #pragma unroll
    for (int mi = 0; mi < 2; mi++) {
        const int r = rowT + wm * 32 + mi * 16 + gr;
        const float inva  = bns[r] * rsqrtf(bnv[r] + EPSB);
        const float beta_a = bnb[r] - bnm[r] * inva;
        const float invb  = bns[r + 8] * rsqrtf(bnv[r + 8] + EPSB);
        const float beta_b = bnb[r + 8] - bnm[r + 8] * invb;
        const size_t ro0 = (size_t)bz * ((size_t)CCH * NPIX) + (size_t)r * NPIX;
        const size_t ro1 = ro0 + 8 * (size_t)NPIX;
        const float* rs0 = SECOND ? Res + ro0 : nullptr;
        const float* rs1 = SECOND ? Res + ro1 : nullptr;
        #pragma unroll
        for (int ni = 0; ni < 4; ni++) {
            const int c = colT + wn * 32 + ni * 8 + (tg << 1);
            float v0 = acc[mi][ni][0] * inva + beta_a;
            float v1 = acc[mi][ni][1] * inva + beta_a;
            float v2 = acc[mi][ni][2] * invb + beta_b;
            float v3 = acc[mi][ni][3] * invb + beta_b;
            if (SECOND) {
                float2 f0 = *(const float2*)(rs0 + c);
                float2 f1 = *(const float2*)(rs1 + c);
                v0 = fmaxf(v0 + f0.x, 0.f) + f0.x;
                v1 = fmaxf(v1 + f0.y, 0.f) + f0.y;
                v2 = fmaxf(v2 + f1.x, 0.f) + f1.x;
                v3 = fmaxf(v3 + f1.y, 0.f) + f1.y;
            } else {
                v0 = rna32(fmaxf(v0, 0.f)); v1 = rna32(fmaxf(v1, 0.f));
                v2 = rna32(fmaxf(v2, 0.f)); v3 = rna32(fmaxf(v3, 0.f));
            }
            *(float2*)(Out + ro0 + c) = make_float2(v0, v1);
            *(float2*)(Out + ro1 + c) = make_float2(v2, v3);
        }
    }
}

// ===========================================================================
// Row softmax; fp32 scores -> split-bf16 attn planes
// ===========================================================================
__global__ __launch_bounds__(256) void k_softmax(const float* __restrict__ S,
                                                 bf16* __restrict__ Ah,
                                                 bf16* __restrict__ Al)
{
    const size_t base = (size_t)blockIdx.x * NPIX;
    const float* p = S + base;
    const int tid = threadIdx.x;
    float v[9];
    float mx = -1e30f;
    #pragma unroll
    for (int i = 0; i < 9; i++) {
        v[i] = p[tid + (i << 8)];
        mx = fmaxf(mx, v[i]);
    }
    __shared__ float red[8];
    #pragma unroll
    for (int o = 16; o > 0; o >>= 1)
        mx = fmaxf(mx, __shfl_xor_sync(0xffffffffu, mx, o));
    if ((tid & 31) == 0) red[tid >> 5] = mx;
    __syncthreads();
    float m2 = red[0];
    #pragma unroll
    for (int i = 1; i < 8; i++) m2 = fmaxf(m2, red[i]);
    __syncthreads();
    float s = 0.f;
    #pragma unroll
    for (int i = 0; i < 9; i++) { v[i] = __expf(v[i] - m2); s += v[i]; }
    #pragma unroll
    for (int o = 16; o > 0; o >>= 1)
        s += __shfl_xor_sync(0xffffffffu, s, o);
    if ((tid & 31) == 0) red[tid >> 5] = s;
    __syncthreads();
    float s2 = 0.f;
    #pragma unroll
    for (int i = 0; i < 8; i++) s2 += red[i];
    const float inv = 1.0f / s2;
    #pragma unroll
    for (int i = 0; i < 9; i++) {
        bf16 h, l;
        spl(v[i] * inv, h, l);
        Ah[base + tid + (i << 8)] = h;
        Al[base + tid + (i << 8)] = l;
    }
}

// ===========================================================================
// Host launcher
// ===========================================================================
extern "C" void kernel_launch(void* const* d_in, const int* in_sizes, int n_in,
                              void* d_out, int out_size)
{
    (void)in_sizes; (void)n_in; (void)out_size;
    const float* F_b  = (const float*)d_in[0];
    const float* F_a  = (const float*)d_in[1];
    const float* qw   = (const float*)d_in[2];
    const float* qb   = (const float*)d_in[3];
    const float* kw   = (const float*)d_in[4];
    const float* kb   = (const float*)d_in[5];
    const float* vw   = (const float*)d_in[6];
    const float* vb   = (const float*)d_in[7];
    const float* c1w  = (const float*)d_in[8];
    const float* bn1s = (const float*)d_in[9];
    const float* bn1b = (const float*)d_in[10];
    const float* bn1m = (const float*)d_in[11];
    const float* bn1v = (const float*)d_in[12];
    const float* c2w  = (const float*)d_in[13];
    const float* bn2s = (const float*)d_in[14];
    const float* bn2b = (const float*)d_in[15];
    const float* bn2m = (const float*)d_in[16];
    const float* bn2v = (const float*)d_in[17];
    float* out = (float*)d_out;

    float *scores, *fused, *ft32, *tt32, *c1t, *c2t;
    bf16 *Fbh,*Fbl,*Fah,*Fal,*qwh,*qwl,*kwh,*kwl,*vwh,*vwl;
    bf16 *Qh,*Ql,*Kh,*Kl,*Vh,*Vl,*Ath,*Atl;
    cudaGetSymbolAddress((void**)&scores, g_scores);
    cudaGetSymbolAddress((void**)&fused,  g_fused);
    cudaGetSymbolAddress((void**)&ft32,   g_ft32);
    cudaGetSymbolAddress((void**)&tt32,   g_tt32);
    cudaGetSymbolAddress((void**)&c1t,    g_c1t);
    cudaGetSymbolAddress((void**)&c2t,    g_c2t);
    cudaGetSymbolAddress((void**)&Fbh, g_Fbh); cudaGetSymbolAddress((void**)&Fbl, g_Fbl);
    cudaGetSymbolAddress((void**)&Fah, g_Fah); cudaGetSymbolAddress((void**)&Fal, g_Fal);
    cudaGetSymbolAddress((void**)&qwh, g_qwh); cudaGetSymbolAddress((void**)&qwl, g_qwl);
    cudaGetSymbolAddress((void**)&kwh, g_kwh); cudaGetSymbolAddress((void**)&kwl, g_kwl);
    cudaGetSymbolAddress((void**)&vwh, g_vwh); cudaGetSymbolAddress((void**)&vwl, g_vwl);
    cudaGetSymbolAddress((void**)&Qh,  g_Qh);  cudaGetSymbolAddress((void**)&Ql,  g_Ql);
    cudaGetSymbolAddress((void**)&Kh,  g_Kh);  cudaGetSymbolAddress((void**)&Kl,  g_Kl);
    cudaGetSymbolAddress((void**)&Vh,  g_Vh);  cudaGetSymbolAddress((void**)&Vl,  g_Vl);
    cudaGetSymbolAddress((void**)&Ath, g_Ath); cudaGetSymbolAddress((void**)&Atl, g_Atl);

    const int STG_MK = 2 * (BMT * AK_PAD * 2) + 2 * (BKT * BN_PAD * 2);
    const int STG_KM = 2 * (BKT * AM_PAD * 2) + 2 * (BKT * BN_PAD * 2);
    const int SMEM_MK = 3 * STG_MK;        // 89088
    const int SMEM_KM = 3 * STG_KM;        // 79872
    const int SMEM_CV = 2 * STG32;         // 73728

    cudaFuncSetAttribute((const void*)k_mm<E_BROW, false, false, true,  false>, cudaFuncAttributeMaxDynamicSharedMemorySize, SMEM_MK);
    cudaFuncSetAttribute((const void*)k_mm<E_NONE, true,  true,  false, false>, cudaFuncAttributeMaxDynamicSharedMemorySize, SMEM_KM);
    cudaFuncSetAttribute((const void*)k_mm<E_RES,  false, true,  false, true >, cudaFuncAttributeMaxDynamicSharedMemorySize, SMEM_MK);
    cudaFuncSetAttribute((const void*)k_conv32<false>, cudaFuncAttributeMaxDynamicSharedMemorySize, SMEM_CV);
    cudaFuncSetAttribute((const void*)k_conv32<true>,  cudaFuncAttributeMaxDynamicSharedMemorySize, SMEM_CV);

    dim3 blk(256);
    dim3 gFeat(NPIX / BNT, CCH / BMT, BBATCH);
    dim3 gScor(NPIX / BNT, NPIX / BMT, BBATCH);
    const size_t FS = (size_t)CCH * NPIX;
    const size_t AS = (size_t)NPIX * NPIX;

    // preconvert
    k_cvt<<<(int)(FSZ/4/256), blk>>>(F_b, Fbh, Fbl, (int)(FSZ/4));
    k_cvt<<<(int)(FSZ/4/256), blk>>>(F_a, Fah, Fal, (int)(FSZ/4));
    k_cvt<<<CCH*CCH/4/256, blk>>>(qw, qwh, qwl, CCH*CCH/4);
    k_cvt<<<CCH*CCH/4/256, blk>>>(kw, kwh, kwl, CCH*CCH/4);
    k_cvt<<<CCH*CCH/4/256, blk>>>(vw, vwh, vwl, CCH*CCH/4);
    k_cvt32<<<CCH*KCONV/4/256, blk>>>(c1w, c1t, CCH*KCONV/4);
    k_cvt32<<<CCH*KCONV/4/256, blk>>>(c2w, c2t, CCH*KCONV/4);

    // Q, K, V (bf16 planes out)
    k_mm<E_BROW, false, false, true, false><<<gFeat, blk, SMEM_MK>>>(
        qwh, qwl, 0, CCH, Fbh, Fbl, FS, NPIX, CCH,
        nullptr, Qh, Ql, nullptr, FS, NPIX, qb, nullptr, 0);
    k_mm<E_BROW, false, false, true, false><<<gFeat, blk, SMEM_MK>>>(
        kwh, kwl, 0, CCH, Fah, Fal, FS, NPIX, CCH,
        nullptr, Kh, Kl, nullptr, FS, NPIX, kb, nullptr, 0);
    k_mm<E_BROW, false, false, true, false><<<gFeat, blk, SMEM_MK>>>(
        vwh, vwl, 0, CCH, Fah, Fal, FS, NPIX, CCH,
        nullptr, Vh, Vl, nullptr, FS, NPIX, vb, nullptr, 0);

    // scores (fp32)
    k_mm<E_NONE, true, true, false, false><<<gScor, blk, SMEM_KM>>>(
        Kh, Kl, FS, NPIX, Qh, Ql, FS, NPIX, CCH,
        scores, nullptr, nullptr, nullptr, AS, NPIX, nullptr, nullptr, 0);

    // softmax -> attn planes
    k_softmax<<<BBATCH * NPIX, blk>>>(scores, Ath, Atl);

    // fused = V @ attn + F_b  (exact fp32 + tf32-rounded plane)
    k_mm<E_RES, false, true, false, true><<<gFeat, blk, SMEM_MK>>>(
        Vh, Vl, FS, NPIX, Ath, Atl, AS, NPIX, NPIX,
        fused, nullptr, nullptr, ft32, FS, NPIX, nullptr, F_b, FS);

    // conv1 (tf32) + bn1 + relu -> tt32 ; conv2 (tf32) + bn2 + res -> out
    k_conv32<false><<<gFeat, blk, SMEM_CV>>>(
        c1t, ft32, bn1s, bn1b, bn1m, bn1v, nullptr, tt32);
    k_conv32<true><<<gFeat, blk, SMEM_CV>>>(
        c2t, tt32, bn2s, bn2b, bn2m, bn2v, fused, out);
}

// round 11
// speedup vs baseline: 1.1231x; 1.0262x over previous
#include <cuda_runtime.h>
#include <cuda_bf16.h>
#include <cstdint>

#define BBATCH 16
#define CCH    256
#define HHH    48
#define WWW    48
#define NPIX   2304
#define KCONV  2304
#define EPSB   1e-5f

#define BMT 128
#define BNT 64
#define BKT 32

#define AK_PAD 40     // bf16 A [m][k] rows: 80B
#define AM_PAD 136    // bf16 A [k][m] rows (TA): 272B
#define BN_PAD 72     // bf16 B [k][n] rows: 144B

typedef __nv_bfloat16 bf16;

// ---------------- scratch ----------------
#define FSZ  ((size_t)BBATCH * CCH * NPIX)
#define ASZG ((size_t)BBATCH * NPIX * NPIX)

__device__ float g_scores[ASZG];         // scores, then tf32 attn in place
__device__ float g_fused [FSZ];          // exact fp32 (residual)
__device__ float g_ft32  [FSZ];          // tf32-rounded fused (conv1 input)
__device__ float g_tt32  [FSZ];          // tf32-rounded tmp   (conv2 input)
__device__ float g_vt32  [FSZ];          // tf32-rounded V     (AV input)
__device__ float g_c1t   [CCH*KCONV];
__device__ float g_c2t   [CCH*KCONV];

__device__ __align__(16) bf16 g_Fbh[FSZ], g_Fbl[FSZ], g_Fah[FSZ], g_Fal[FSZ];
__device__ __align__(16) bf16 g_qwh[CCH*CCH], g_qwl[CCH*CCH];
__device__ __align__(16) bf16 g_kwh[CCH*CCH], g_kwl[CCH*CCH];
__device__ __align__(16) bf16 g_vwh[CCH*CCH], g_vwl[CCH*CCH];
__device__ __align__(16) bf16 g_Qh[FSZ], g_Ql[FSZ], g_Kh[FSZ], g_Kl[FSZ];

// ---------------- helpers ----------------
__device__ __forceinline__ uint32_t smem_u32(const void* p) {
    uint32_t a;
    asm("{ .reg .u64 t; cvta.to.shared.u64 t, %1; cvt.u32.u64 %0, t; }"
        : "=r"(a) : "l"(p));
    return a;
}
__device__ __forceinline__ uint32_t pk(bf16 a, bf16 b) {
    return (uint32_t)__bfloat16_as_ushort(a) |
           ((uint32_t)__bfloat16_as_ushort(b) << 16);
}
__device__ __forceinline__ void spl(float x, bf16& h, bf16& l) {
    h = __float2bfloat16(x);
    l = __float2bfloat16(x - __bfloat162float(h));
}
__device__ __forceinline__ void wr_bf(bf16* H, bf16* L, size_t off,
                                      float a, float b) {
    bf16 h0, l0, h1, l1;
    spl(a, h0, l0); spl(b, h1, l1);
    *(uint32_t*)(H + off) = pk(h0, h1);
    *(uint32_t*)(L + off) = pk(l0, l1);
}
__device__ __forceinline__ float rna32(float x) {
    uint32_t u;
    asm("cvt.rna.tf32.f32 %0, %1;" : "=r"(u) : "f"(x));
    return __uint_as_float(u);
}

#define CPA(d, s)     asm volatile("cp.async.cg.shared.global [%0], [%1], 16;" :: "r"(d), "l"(s))
#define CPA_COMMIT()  asm volatile("cp.async.commit_group;")
#define CPA_WAIT0()   asm volatile("cp.async.wait_group 0;")
#define CPA_WAIT1()   asm volatile("cp.async.wait_group 1;")

#define LDMX4(R, addr) \
    asm volatile("ldmatrix.sync.aligned.m8n8.x4.shared.b16 {%0,%1,%2,%3}, [%4];" \
        : "=r"((R)[0]), "=r"((R)[1]), "=r"((R)[2]), "=r"((R)[3]) : "r"(addr))
#define LDMX4T(R, addr) \
    asm volatile("ldmatrix.sync.aligned.m8n8.x4.trans.shared.b16 {%0,%1,%2,%3}, [%4];" \
        : "=r"((R)[0]), "=r"((R)[1]), "=r"((R)[2]), "=r"((R)[3]) : "r"(addr))
#define MMA16816(d, a, b) \
    asm volatile("mma.sync.aligned.m16n8k16.row.col.f32.bf16.bf16.f32 " \
        "{%0,%1,%2,%3}, {%4,%5,%6,%7}, {%8,%9}, {%0,%1,%2,%3};" \
        : "+f"((d)[0]), "+f"((d)[1]), "+f"((d)[2]), "+f"((d)[3]) \
        : "r"((a)[0]), "r"((a)[1]), "r"((a)[2]), "r"((a)[3]), \
          "r"((b)[0]), "r"((b)[1]))
#define MMATF32(d, a, b) \
    asm volatile("mma.sync.aligned.m16n8k8.row.col.f32.tf32.tf32.f32 " \
        "{%0,%1,%2,%3}, {%4,%5,%6,%7}, {%8,%9}, {%0,%1,%2,%3};" \
        : "+f"((d)[0]), "+f"((d)[1]), "+f"((d)[2]), "+f"((d)[3]) \
        : "r"((a)[0]), "r"((a)[1]), "r"((a)[2]), "r"((a)[3]), \
          "r"((b)[0]), "r"((b)[1]))

enum { E_NONE = 0, E_BROW = 1 };

// ===========================================================================
// converters
// ===========================================================================
__global__ __launch_bounds__(256) void k_cvt(const float* __restrict__ X,
                                             bf16* __restrict__ H,
                                             bf16* __restrict__ L, int n4)
{
    const int i = blockIdx.x * 256 + threadIdx.x;
    if (i >= n4) return;
    float4 v = *(const float4*)(X + (size_t)i * 4);
    bf16 h0,l0,h1,l1,h2,l2,h3,l3;
    spl(v.x,h0,l0); spl(v.y,h1,l1); spl(v.z,h2,l2); spl(v.w,h3,l3);
    *(uint2*)(H + (size_t)i * 4) = make_uint2(pk(h0,h1), pk(h2,h3));
    *(uint2*)(L + (size_t)i * 4) = make_uint2(pk(l0,l1), pk(l2,l3));
}
__global__ __launch_bounds__(256) void k_cvt32(const float* __restrict__ X,
                                               float* __restrict__ T, int n4)
{
    const int i = blockIdx.x * 256 + threadIdx.x;
    if (i >= n4) return;
    float4 v = *(const float4*)(X + (size_t)i * 4);
    v.x = rna32(v.x); v.y = rna32(v.y); v.z = rna32(v.z); v.w = rna32(v.w);
    *(float4*)(T + (size_t)i * 4) = v;
}

// ===========================================================================
// bf16 split HMMA GEMM (Q/K/V, scores), 3-stage cp.async
// ===========================================================================
template <int EPI, bool TA, bool OF32, bool OBF, bool OT32>
__global__ __launch_bounds__(256, 2) void k_mm(
    const bf16* __restrict__ Ah, const bf16* __restrict__ Al,
    size_t Abs, int lda,
    const bf16* __restrict__ Bh, const bf16* __restrict__ Bl,
    size_t Bbs, int ldb, int Ktot,
    float* __restrict__ D, bf16* __restrict__ Dh, bf16* __restrict__ Dl,
    float* __restrict__ Dt,
    size_t Dbs, int ldd,
    const float* __restrict__ bias)
{
    extern __shared__ char sm[];
    constexpr int ASZ = TA ? (BKT * AM_PAD * 2) : (BMT * AK_PAD * 2);
    constexpr int BSZ = BKT * BN_PAD * 2;
    constexpr int STG = 2 * ASZ + 2 * BSZ;

    const int tid = threadIdx.x, wid = tid >> 5, lane = tid & 31;
    const int wm = wid & 3, wn = wid >> 2;
    const int colT = blockIdx.x * BNT, rowT = blockIdx.y * BMT, bz = blockIdx.z;
    const uint32_t su = smem_u32(sm);

    const bf16* Ah_b = Ah + (size_t)bz * Abs;
    const bf16* Al_b = Al + (size_t)bz * Abs;
    const bf16* Bh_b = Bh + (size_t)bz * Bbs;
    const bf16* Bl_b = Bl + (size_t)bz * Bbs;

    float acc[2][4][4];
    #pragma unroll
    for (int i = 0; i < 2; i++)
        #pragma unroll
        for (int j = 0; j < 4; j++)
            #pragma unroll
            for (int q = 0; q < 4; q++) acc[i][j][q] = 0.f;

    auto cpa = [&](int k0, int s) {
        const uint32_t base = su + s * STG;
        if constexpr (!TA) {
            #pragma unroll
            for (int i = 0; i < 2; i++) {
                const int idx = tid + (i << 8);
                const int row = idx >> 2, c4 = idx & 3;
                const size_t so = (size_t)(rowT + row) * lda + k0 + c4 * 8;
                const uint32_t d = base + (uint32_t)row * (AK_PAD * 2) + c4 * 16;
                CPA(d, Ah_b + so);
                CPA(d + ASZ, Al_b + so);
            }
        } else {
            #pragma unroll
            for (int i = 0; i < 2; i++) {
                const int idx = tid + (i << 8);
                const int row = idx >> 4, c16 = idx & 15;
                const size_t so = (size_t)(k0 + row) * lda + rowT + c16 * 8;
                const uint32_t d = base + (uint32_t)row * (AM_PAD * 2) + c16 * 16;
                CPA(d, Ah_b + so);
                CPA(d + ASZ, Al_b + so);
            }
        }
        const int row = tid >> 3, c8 = tid & 7;
        const size_t so = (size_t)(k0 + row) * ldb + colT + c8 * 8;
        const uint32_t d = base + 2 * ASZ + (uint32_t)row * (BN_PAD * 2) + c8 * 16;
        CPA(d, Bh_b + so);
        CPA(d + BSZ, Bl_b + so);
    };

    const int mtx = lane >> 3, r8 = lane & 7;
    uint32_t aoff[2][2];
    #pragma unroll
    for (int mi = 0; mi < 2; mi++)
        #pragma unroll
        for (int ks = 0; ks < 2; ks++) {
            if constexpr (!TA) {
                const int row = wm * 32 + mi * 16 + (mtx & 1) * 8 + r8;
                const int kc  = ks * 16 + (mtx >> 1) * 8;
                aoff[mi][ks] = (uint32_t)row * (AK_PAD * 2) + kc * 2;
            } else {
                const int kk = ks * 16 + (mtx >> 1) * 8 + r8;
                const int mm = wm * 32 + mi * 16 + (mtx & 1) * 8;
                aoff[mi][ks] = (uint32_t)kk * (AM_PAD * 2) + mm * 2;
            }
        }
    uint32_t boff[2][2];
    #pragma unroll
    for (int ni2 = 0; ni2 < 2; ni2++)
        #pragma unroll
        for (int ks = 0; ks < 2; ks++) {
            const int kb = ks * 16 + (mtx & 1) * 8 + r8;
            const int nb = wn * 32 + ni2 * 16 + (mtx >> 1) * 8;
            boff[ni2][ks] = (uint32_t)kb * (BN_PAD * 2) + nb * 2;
        }

    const int nch = Ktot / BKT;
    cpa(0, 0);
    CPA_COMMIT();
    if (nch > 1) { cpa(BKT, 1); CPA_COMMIT(); }

    int s = 0;
    for (int i = 0; i < nch; i++) {
        if (i + 1 < nch) CPA_WAIT1(); else CPA_WAIT0();
        __syncthreads();
        if (i + 2 < nch) {
            int s2 = s + 2; if (s2 >= 3) s2 -= 3;
            cpa((i + 2) * BKT, s2);
            CPA_COMMIT();
        }
        const uint32_t aHi = su + s * STG;
        const uint32_t aLo = aHi + ASZ;
        const uint32_t bHi = aHi + 2 * ASZ;
        const uint32_t bLo = bHi + BSZ;

        #pragma unroll
        for (int ks = 0; ks < 2; ks++) {
            uint32_t ah[2][4], al[2][4];
            #pragma unroll
            for (int mi = 0; mi < 2; mi++) {
                if constexpr (!TA) {
                    LDMX4(ah[mi], aHi + aoff[mi][ks]);
                    LDMX4(al[mi], aLo + aoff[mi][ks]);
                } else {
                    LDMX4T(ah[mi], aHi + aoff[mi][ks]);
                    LDMX4T(al[mi], aLo + aoff[mi][ks]);
                }
            }
            #pragma unroll
            for (int ni2 = 0; ni2 < 2; ni2++) {
                uint32_t bh[4], bl[4];
                LDMX4T(bh, bHi + boff[ni2][ks]);
                LDMX4T(bl, bLo + boff[ni2][ks]);
                #pragma unroll
                for (int mi = 0; mi < 2; mi++) {
                    #pragma unroll
                    for (int nf = 0; nf < 2; nf++) {
                        float* ac = acc[mi][ni2 * 2 + nf];
                        MMA16816(ac, ah[mi], bh + nf * 2);
                        MMA16816(ac, ah[mi], bl + nf * 2);
                        MMA16816(ac, al[mi], bh + nf * 2);
                    }
                }
            }
        }
        s += 1; if (s >= 3) s = 0;
    }

    // epilogue
    #pragma unroll
    for (int mi = 0; mi < 2; mi++) {
        const int r = rowT + wm * 32 + mi * 16 + (lane >> 2);
        float ba = 0.f, bb_ = 0.f;
        if (EPI == E_BROW) { ba = bias[r]; bb_ = bias[r + 8]; }
        const size_t ro0 = (size_t)bz * Dbs + (size_t)r * ldd;
        const size_t ro1 = ro0 + 8 * (size_t)ldd;
        #pragma unroll
        for (int ni = 0; ni < 4; ni++) {
            const int c = colT + wn * 32 + ni * 8 + ((lane & 3) << 1);
            float v0 = acc[mi][ni][0], v1 = acc[mi][ni][1];
            float v2 = acc[mi][ni][2], v3 = acc[mi][ni][3];
            if (EPI == E_BROW) {
                v0 += ba; v1 += ba; v2 += bb_; v3 += bb_;
            }
            if (OF32) {
                *(float2*)(D + ro0 + c) = make_float2(v0, v1);
                *(float2*)(D + ro1 + c) = make_float2(v2, v3);
            }
            if (OBF) {
                wr_bf(Dh, Dl, ro0 + c, v0, v1);
                wr_bf(Dh, Dl, ro1 + c, v2, v3);
            }
            if (OT32) {
                *(float2*)(Dt + ro0 + c) = make_float2(rna32(v0), rna32(v1));
                *(float2*)(Dt + ro1 + c) = make_float2(rna32(v2), rna32(v3));
            }
        }
    }
}

// ===========================================================================
// tf32 tile core constants (shared by conv32 / av32)
// A [128][36]fl pad (144B rows), B [32][72]fl pad (288B rows)
// ===========================================================================
#define ASZ32 (128 * 36 * 4)
#define BSZ32 (32 * 72 * 4)
#define STG32 (ASZ32 + BSZ32)

// ===========================================================================
// tf32 implicit-GEMM 3x3 conv + BN epilogues
// ===========================================================================
template <bool SECOND>
__global__ __launch_bounds__(256, 2) void k_conv32(
    const float* __restrict__ Wt,
    const float* __restrict__ In,
    const float* __restrict__ bns, const float* __restrict__ bnb,
    const float* __restrict__ bnm, const float* __restrict__ bnv,
    const float* __restrict__ Res,
    float* __restrict__ Out)
{
    extern __shared__ char sm[];
    const int tid = threadIdx.x, wid = tid >> 5, lane = tid & 31;
    const int wm = wid & 3, wn = wid >> 2;
    const int colT = blockIdx.x * BNT, rowT = blockIdx.y * BMT, bz = blockIdx.z;
    const uint32_t su = smem_u32(sm);
    const float* Inb = In + (size_t)bz * (size_t)CCH * NPIX;

    float acc[2][4][4];
    #pragma unroll
    for (int i = 0; i < 2; i++)
        #pragma unroll
        for (int j = 0; j < 4; j++)
            #pragma unroll
            for (int q = 0; q < 4; q++) acc[i][j][q] = 0.f;

    auto cpaA = [&](int k0, int s) {
        const uint32_t base = su + s * STG32;
        #pragma unroll
        for (int i = 0; i < 4; i++) {
            const int idx = tid + (i << 8);
            const int row = idx >> 3, c4 = idx & 7;
            const size_t so = (size_t)(rowT + row) * KCONV + k0 + c4 * 4;
            CPA(base + (uint32_t)row * 144 + c4 * 16, Wt + so);
        }
    };
    float bst[8];
    auto ldB = [&](int k0) {
        #pragma unroll
        for (int j = 0; j < 2; j++) {
            const int kg = k0 + (tid >> 4) + j * 16;
            const int c  = kg / 9;
            const int r  = kg - c * 9;
            const int ky = r / 3;
            const int kx = r - ky * 3;
            const size_t cb = (size_t)c * NPIX;
            #pragma unroll
            for (int u = 0; u < 4; u++) {
                const int p = colT + ((tid & 15) << 2) + u;
                const int y = p / WWW, x = p - y * WWW;
                const int sy = y + ky - 1, sx = x + kx - 1;
                const bool ok = (unsigned)sy < (unsigned)HHH &&
                                (unsigned)sx < (unsigned)WWW;
                bst[j * 4 + u] = ok ? Inb[cb + sy * WWW + sx] : 0.f;
            }
        }
    };
    auto stsB = [&](int s) {
        const uint32_t base = su + s * STG32 + ASZ32;
        #pragma unroll
        for (int j = 0; j < 2; j++) {
            const uint32_t d = base + (uint32_t)((tid >> 4) + j * 16) * 288
                               + ((tid & 15) << 4);
            asm volatile("st.shared.v4.b32 [%0], {%1,%2,%3,%4};"
                :: "r"(d), "r"(__float_as_uint(bst[j*4+0])),
                   "r"(__float_as_uint(bst[j*4+1])),
                   "r"(__float_as_uint(bst[j*4+2])),
                   "r"(__float_as_uint(bst[j*4+3])) : "memory");
        }
    };

    const int gr = lane >> 2, tg = lane & 3;
    uint32_t a0off[2];
    #pragma unroll
    for (int mi = 0; mi < 2; mi++)
        a0off[mi] = (uint32_t)(wm * 32 + mi * 16 + gr) * 144 + tg * 4;
    uint32_t b0off[4];
    #pragma unroll
    for (int ni = 0; ni < 4; ni++)
        b0off[ni] = ASZ32 + (uint32_t)tg * 288
                    + (uint32_t)(wn * 32 + ni * 8 + gr) * 4;

    const int nch = KCONV / BKT;
    cpaA(0, 0);
    CPA_COMMIT();
    ldB(0); stsB(0);
    CPA_WAIT0();
    __syncthreads();

    for (int i = 0; i < nch; i++) {
        const int s = i & 1;
        if (i + 1 < nch) {
            cpaA((i + 1) * BKT, s ^ 1);
            CPA_COMMIT();
            ldB((i + 1) * BKT);
        }
        const uint32_t base = su + s * STG32;
        #pragma unroll
        for (int ks = 0; ks < 4; ks++) {
            uint32_t a[2][4], b[4][2];
            #pragma unroll
            for (int mi = 0; mi < 2; mi++) {
                const uint32_t a0 = base + a0off[mi] + ks * 32;
                asm volatile("ld.shared.b32 %0, [%1];" : "=r"(a[mi][0]) : "r"(a0));
                asm volatile("ld.shared.b32 %0, [%1];" : "=r"(a[mi][1]) : "r"(a0 + 8*144));
                asm volatile("ld.shared.b32 %0, [%1];" : "=r"(a[mi][2]) : "r"(a0 + 16));
                asm volatile("ld.shared.b32 %0, [%1];" : "=r"(a[mi][3]) : "r"(a0 + 8*144 + 16));
            }
            #pragma unroll
            for (int ni = 0; ni < 4; ni++) {
                const uint32_t b0 = base + b0off[ni] + ks * 2304;
                asm volatile("ld.shared.b32 %0, [%1];" : "=r"(b[ni][0]) : "r"(b0));
                asm volatile("ld.shared.b32 %0, [%1];" : "=r"(b[ni][1]) : "r"(b0 + 4*288));
            }
            #pragma unroll
            for (int mi = 0; mi < 2; mi++)
                #pragma unroll
                for (int ni = 0; ni < 4; ni++)
                    MMATF32(acc[mi][ni], a[mi], b[ni]);
        }
        if (i + 1 < nch) { stsB(s ^ 1); CPA_WAIT0(); }
        __syncthreads();
    }

    #pragma unroll
    for (int mi = 0; mi < 2; mi++) {
        const int r = rowT + wm * 32 + mi * 16 + gr;
        const float inva   = bns[r] * rsqrtf(bnv[r] + EPSB);
        const float beta_a = bnb[r] - bnm[r] * inva;
        const float invb   = bns[r + 8] * rsqrtf(bnv[r + 8] + EPSB);
        const float beta_b = bnb[r + 8] - bnm[r + 8] * invb;
        const size_t ro0 = (size_t)bz * ((size_t)CCH * NPIX) + (size_t)r * NPIX;
        const size_t ro1 = ro0 + 8 * (size_t)NPIX;
        const float* rs0 = SECOND ? Res + ro0 : nullptr;
        const float* rs1 = SECOND ? Res + ro1 : nullptr;
        #pragma unroll
        for (int ni = 0; ni < 4; ni++) {
            const int c = colT + wn * 32 + ni * 8 + (tg << 1);
            float v0 = acc[mi][ni][0] * inva + beta_a;
            float v1 = acc[mi][ni][1] * inva + beta_a;
            float v2 = acc[mi][ni][2] * invb + beta_b;
            float v3 = acc[mi][ni][3] * invb + beta_b;
            if (SECOND) {
                float2 f0 = *(const float2*)(rs0 + c);
                float2 f1 = *(const float2*)(rs1 + c);
                v0 = fmaxf(v0 + f0.x, 0.f) + f0.x;
                v1 = fmaxf(v1 + f0.y, 0.f) + f0.y;
                v2 = fmaxf(v2 + f1.x, 0.f) + f1.x;
                v3 = fmaxf(v3 + f1.y, 0.f) + f1.y;
            } else {
                v0 = rna32(fmaxf(v0, 0.f)); v1 = rna32(fmaxf(v1, 0.f));
                v2 = rna32(fmaxf(v2, 0.f)); v3 = rna32(fmaxf(v3, 0.f));
            }
            *(float2*)(Out + ro0 + c) = make_float2(v0, v1);
            *(float2*)(Out + ro1 + c) = make_float2(v2, v3);
        }
    }
}

// ===========================================================================
// tf32 AV GEMM: fused[c][m] = sum_n V[c][n]*attn[n][m] + F_b[c][m]
// Writes exact fp32 fused + tf32-rounded ft32. Same tf32 tile as conv32.
// ===========================================================================
__global__ __launch_bounds__(256, 2) void k_av32(
    const float* __restrict__ V32,    // [b][256][2304] tf32-rounded
    const float* __restrict__ At32,   // [b][2304][2304] tf32-rounded attn
    const float* __restrict__ Fb,     // residual
    float* __restrict__ Dfull, float* __restrict__ Dt32)
{
    extern __shared__ char sm[];
    const int tid = threadIdx.x, wid = tid >> 5, lane = tid & 31;
    const int wm = wid & 3, wn = wid >> 2;
    const int colT = blockIdx.x * BNT, rowT = blockIdx.y * BMT, bz = blockIdx.z;
    const uint32_t su = smem_u32(sm);
    const float* Vb = V32  + (size_t)bz * (size_t)CCH * NPIX;
    const float* Ab = At32 + (size_t)bz * (size_t)NPIX * NPIX;

    float acc[2][4][4];
    #pragma unroll
    for (int i = 0; i < 2; i++)
        #pragma unroll
        for (int j = 0; j < 4; j++)
            #pragma unroll
            for (int q = 0; q < 4; q++) acc[i][j][q] = 0.f;

    auto cpa = [&](int k0, int s) {
        const uint32_t base = su + s * STG32;
        #pragma unroll
        for (int i = 0; i < 4; i++) {
            const int idx = tid + (i << 8);
            const int row = idx >> 3, c4 = idx & 7;
            const size_t so = (size_t)(rowT + row) * NPIX + k0 + c4 * 4;
            CPA(base + (uint32_t)row * 144 + c4 * 16, Vb + so);
        }
        #pragma unroll
        for (int i = 0; i < 2; i++) {
            const int idx = tid + (i << 8);
            const int row = idx >> 4, c16 = idx & 15;
            const size_t so = (size_t)(k0 + row) * NPIX + colT + c16 * 4;
            CPA(base + ASZ32 + (uint32_t)row * 288 + c16 * 16, Ab + so);
        }
    };

    const int gr = lane >> 2, tg = lane & 3;
    uint32_t a0off[2];
    #pragma unroll
    for (int mi = 0; mi < 2; mi++)
        a0off[mi] = (uint32_t)(wm * 32 + mi * 16 + gr) * 144 + tg * 4;
    uint32_t b0off[4];
    #pragma unroll
    for (int ni = 0; ni < 4; ni++)
        b0off[ni] = ASZ32 + (uint32_t)tg * 288
                    + (uint32_t)(wn * 32 + ni * 8 + gr) * 4;

    const int nch = NPIX / BKT;   // 72
    cpa(0, 0);
    CPA_COMMIT();
    CPA_WAIT0();
    __syncthreads();

    for (int i = 0; i < nch; i++) {
        const int s = i & 1;
        if (i + 1 < nch) {
            cpa((i + 1) * BKT, s ^ 1);
            CPA_COMMIT();
        }
        const uint32_t base = su + s * STG32;
        #pragma unroll
        for (int ks = 0; ks < 4; ks++) {
            uint32_t a[2][4], b[4][2];
            #pragma unroll
            for (int mi = 0; mi < 2; mi++) {
                const uint32_t a0 = base + a0off[mi] + ks * 32;
                asm volatile("ld.shared.b32 %0, [%1];" : "=r"(a[mi][0]) : "r"(a0));
                asm volatile("ld.shared.b32 %0, [%1];" : "=r"(a[mi][1]) : "r"(a0 + 8*144));
                asm volatile("ld.shared.b32 %0, [%1];" : "=r"(a[mi][2]) : "r"(a0 + 16));
                asm volatile("ld.shared.b32 %0, [%1];" : "=r"(a[mi][3]) : "r"(a0 + 8*144 + 16));
            }
            #pragma unroll
            for (int ni = 0; ni < 4; ni++) {
                const uint32_t b0 = base + b0off[ni] + ks * 2304;
                asm volatile("ld.shared.b32 %0, [%1];" : "=r"(b[ni][0]) : "r"(b0));
                asm volatile("ld.shared.b32 %0, [%1];" : "=r"(b[ni][1]) : "r"(b0 + 4*288));
            }
            #pragma unroll
            for (int mi = 0; mi < 2; mi++)
                #pragma unroll
                for (int ni = 0; ni < 4; ni++)
                    MMATF32(acc[mi][ni], a[mi], b[ni]);
        }
        if (i + 1 < nch) CPA_WAIT0();
        __syncthreads();
    }

    #pragma unroll
    for (int mi = 0; mi < 2; mi++) {
        const int r = rowT + wm * 32 + mi * 16 + gr;
        const size_t ro0 = (size_t)bz * ((size_t)CCH * NPIX) + (size_t)r * NPIX;
        const size_t ro1 = ro0 + 8 * (size_t)NPIX;
        const float* rs0 = Fb + ro0;
        const float* rs1 = Fb + ro1;
        #pragma unroll
        for (int ni = 0; ni < 4; ni++) {
            const int c = colT + wn * 32 + ni * 8 + (tg << 1);
            float2 f0 = *(const float2*)(rs0 + c);
            float2 f1 = *(const float2*)(rs1 + c);
            const float v0 = acc[mi][ni][0] + f0.x;
            const float v1 = acc[mi][ni][1] + f0.y;
            const float v2 = acc[mi][ni][2] + f1.x;
            const float v3 = acc[mi][ni][3] + f1.y;
            *(float2*)(Dfull + ro0 + c) = make_float2(v0, v1);
            *(float2*)(Dfull + ro1 + c) = make_float2(v2, v3);
            *(float2*)(Dt32 + ro0 + c) = make_float2(rna32(v0), rna32(v1));
            *(float2*)(Dt32 + ro1 + c) = make_float2(rna32(v2), rna32(v3));
        }
    }
}

// ===========================================================================
// Row softmax in place; output tf32-rounded attn (fp32 storage)
// ===========================================================================
__global__ __launch_bounds__(256) void k_softmax(float* __restrict__ S)
{
    float* p = S + (size_t)blockIdx.x * NPIX;
    const int tid = threadIdx.x;
    float v[9];
    float mx = -1e30f;
    #pragma unroll
    for (int i = 0; i < 9; i++) {
        v[i] = p[tid + (i << 8)];
        mx = fmaxf(mx, v[i]);
    }
    __shared__ float red[8];
    #pragma unroll
    for (int o = 16; o > 0; o >>= 1)
        mx = fmaxf(mx, __shfl_xor_sync(0xffffffffu, mx, o));
    if ((tid & 31) == 0) red[tid >> 5] = mx;
    __syncthreads();
    float m2 = red[0];
    #pragma unroll
    for (int i = 1; i < 8; i++) m2 = fmaxf(m2, red[i]);
    __syncthreads();
    float s = 0.f;
    #pragma unroll
    for (int i = 0; i < 9; i++) { v[i] = __expf(v[i] - m2); s += v[i]; }
    #pragma unroll
    for (int o = 16; o > 0; o >>= 1)
        s += __shfl_xor_sync(0xffffffffu, s, o);
    if ((tid & 31) == 0) red[tid >> 5] = s;
    __syncthreads();
    float s2 = 0.f;
    #pragma unroll
    for (int i = 0; i < 8; i++) s2 += red[i];
    const float inv = 1.0f / s2;
    #pragma unroll
    for (int i = 0; i < 9; i++)
        p[tid + (i << 8)] = rna32(v[i] * inv);
}

// ===========================================================================
// Host launcher
// ===========================================================================
extern "C" void kernel_launch(void* const* d_in, const int* in_sizes, int n_in,
                              void* d_out, int out_size)
{
    (void)in_sizes; (void)n_in; (void)out_size;
    const float* F_b  = (const float*)d_in[0];
    const float* F_a  = (const float*)d_in[1];
    const float* qw   = (const float*)d_in[2];
    const float* qb   = (const float*)d_in[3];
    const float* kw   = (const float*)d_in[4];
    const float* kb   = (const float*)d_in[5];
    const float* vw   = (const float*)d_in[6];
    const float* vb   = (const float*)d_in[7];
    const float* c1w  = (const float*)d_in[8];
    const float* bn1s = (const float*)d_in[9];
    const float* bn1b = (const float*)d_in[10];
    const float* bn1m = (const float*)d_in[11];
    const float* bn1v = (const float*)d_in[12];
    const float* c2w  = (const float*)d_in[13];
    const float* bn2s = (const float*)d_in[14];
    const float* bn2b = (const float*)d_in[15];
    const float* bn2m = (const float*)d_in[16];
    const float* bn2v = (const float*)d_in[17];
    float* out = (float*)d_out;

    float *scores, *fused, *ft32, *tt32, *vt32, *c1t, *c2t;
    bf16 *Fbh,*Fbl,*Fah,*Fal,*qwh,*qwl,*kwh,*kwl,*vwh,*vwl;
    bf16 *Qh,*Ql,*Kh,*Kl;
    cudaGetSymbolAddress((void**)&scores, g_scores);
    cudaGetSymbolAddress((void**)&fused,  g_fused);
    cudaGetSymbolAddress((void**)&ft32,   g_ft32);
    cudaGetSymbolAddress((void**)&tt32,   g_tt32);
    cudaGetSymbolAddress((void**)&vt32,   g_vt32);
    cudaGetSymbolAddress((void**)&c1t,    g_c1t);
    cudaGetSymbolAddress((void**)&c2t,    g_c2t);
    cudaGetSymbolAddress((void**)&Fbh, g_Fbh); cudaGetSymbolAddress((void**)&Fbl, g_Fbl);
    cudaGetSymbolAddress((void**)&Fah, g_Fah); cudaGetSymbolAddress((void**)&Fal, g_Fal);
    cudaGetSymbolAddress((void**)&qwh, g_qwh); cudaGetSymbolAddress((void**)&qwl, g_qwl);
    cudaGetSymbolAddress((void**)&kwh, g_kwh); cudaGetSymbolAddress((void**)&kwl, g_kwl);
    cudaGetSymbolAddress((void**)&vwh, g_vwh); cudaGetSymbolAddress((void**)&vwl, g_vwl);
    cudaGetSymbolAddress((void**)&Qh,  g_Qh);  cudaGetSymbolAddress((void**)&Ql,  g_Ql);
    cudaGetSymbolAddress((void**)&Kh,  g_Kh);  cudaGetSymbolAddress((void**)&Kl,  g_Kl);

    const int STG_MK = 2 * (BMT * AK_PAD * 2) + 2 * (BKT * BN_PAD * 2);
    const int STG_KM = 2 * (BKT * AM_PAD * 2) + 2 * (BKT * BN_PAD * 2);
    const int SMEM_MK = 3 * STG_MK;        // 89088
    const int SMEM_KM = 3 * STG_KM;        // 79872
    const int SMEM_32 = 2 * STG32;         // 55296

    cudaFuncSetAttribute((const void*)k_mm<E_BROW, false, false, true,  false>, cudaFuncAttributeMaxDynamicSharedMemorySize, SMEM_MK);
    cudaFuncSetAttribute((const void*)k_mm<E_BROW, false, false, false, true >, cudaFuncAttributeMaxDynamicSharedMemorySize, SMEM_MK);
    cudaFuncSetAttribute((const void*)k_mm<E_NONE, true,  true,  false, false>, cudaFuncAttributeMaxDynamicSharedMemorySize, SMEM_KM);
    cudaFuncSetAttribute((const void*)k_av32,           cudaFuncAttributeMaxDynamicSharedMemorySize, SMEM_32);
    cudaFuncSetAttribute((const void*)k_conv32<false>,  cudaFuncAttributeMaxDynamicSharedMemorySize, SMEM_32);
    cudaFuncSetAttribute((const void*)k_conv32<true>,   cudaFuncAttributeMaxDynamicSharedMemorySize, SMEM_32);

    dim3 blk(256);
    dim3 gFeat(NPIX / BNT, CCH / BMT, BBATCH);
    dim3 gScor(NPIX / BNT, NPIX / BMT, BBATCH);
    const size_t FS = (size_t)CCH * NPIX;
    const size_t AS = (size_t)NPIX * NPIX;

    // preconvert
    k_cvt<<<(int)(FSZ/4/256), blk>>>(F_b, Fbh, Fbl, (int)(FSZ/4));
    k_cvt<<<(int)(FSZ/4/256), blk>>>(F_a, Fah, Fal, (int)(FSZ/4));
    k_cvt<<<CCH*CCH/4/256, blk>>>(qw, qwh, qwl, CCH*CCH/4);
    k_cvt<<<CCH*CCH/4/256, blk>>>(kw, kwh, kwl, CCH*CCH/4);
    k_cvt<<<CCH*CCH/4/256, blk>>>(vw, vwh, vwl, CCH*CCH/4);
    k_cvt32<<<CCH*KCONV/4/256, blk>>>(c1w, c1t, CCH*KCONV/4);
    k_cvt32<<<CCH*KCONV/4/256, blk>>>(c2w, c2t, CCH*KCONV/4);

    // Q, K (bf16 planes); V (tf32 plane)
    k_mm<E_BROW, false, false, true, false><<<gFeat, blk, SMEM_MK>>>(
        qwh, qwl, 0, CCH, Fbh, Fbl, FS, NPIX, CCH,
        nullptr, Qh, Ql, nullptr, FS, NPIX, qb);
    k_mm<E_BROW, false, false, true, false><<<gFeat, blk, SMEM_MK>>>(
        kwh, kwl, 0, CCH, Fah, Fal, FS, NPIX, CCH,
        nullptr, Kh, Kl, nullptr, FS, NPIX, kb);
    k_mm<E_BROW, false, false, false, true><<<gFeat, blk, SMEM_MK>>>(
        vwh, vwl, 0, CCH, Fah, Fal, FS, NPIX, CCH,
        nullptr, nullptr, nullptr, vt32, FS, NPIX, vb);

    // scores (fp32)
    k_mm<E_NONE, true, true, false, false><<<gScor, blk, SMEM_KM>>>(
        Kh, Kl, FS, NPIX, Qh, Ql, FS, NPIX, CCH,
        scores, nullptr, nullptr, nullptr, AS, NPIX, nullptr);

    // softmax in place -> tf32 attn
    k_softmax<<<BBATCH * NPIX, blk>>>(scores);

    // fused = V @ attn + F_b  (tf32 MMA; exact fp32 + rounded plane out)
    k_av32<<<gFeat, blk, SMEM_32>>>(vt32, scores, F_b, fused, ft32);

    // conv1 + bn1 + relu -> tt32 ; conv2 + bn2 + residual -> out
    k_conv32<false><<<gFeat, blk, SMEM_32>>>(
        c1t, ft32, bn1s, bn1b, bn1m, bn1v, nullptr, tt32);
    k_conv32<true><<<gFeat, blk, SMEM_32>>>(
        c2t, tt32, bn2s, bn2b, bn2m, bn2v, fused, out);
}

// round 12
// speedup vs baseline: 1.1534x; 1.0270x over previous
#include <cuda_runtime.h>
#include <cuda_bf16.h>
#include <cstdint>

#define BBATCH 16
#define CCH    256
#define HHH    48
#define WWW    48
#define NPIX   2304
#define KCONV  2304
#define EPSB   1e-5f

#define BMT 128
#define BNT 64
#define BKT 32

#define AK_PAD 40
#define BN_PAD 72
#define SC_PAD 136    // scores kernel: [32][136] bf16 tiles (272B rows)

typedef __nv_bfloat16 bf16;

#define FSZ  ((size_t)BBATCH * CCH * NPIX)
#define ASZG ((size_t)BBATCH * NPIX * NPIX)

__device__ float g_scores[ASZG];
__device__ float g_fused [FSZ];
__device__ float g_ft32  [FSZ];
__device__ float g_tt32  [FSZ];
__device__ float g_vt32  [FSZ];
__device__ float g_c1t   [CCH*KCONV];
__device__ float g_c2t   [CCH*KCONV];

__device__ __align__(16) bf16 g_Fbh[FSZ], g_Fbl[FSZ], g_Fah[FSZ], g_Fal[FSZ];
__device__ __align__(16) bf16 g_qwh[CCH*CCH], g_qwl[CCH*CCH];
__device__ __align__(16) bf16 g_kwh[CCH*CCH], g_kwl[CCH*CCH];
__device__ __align__(16) bf16 g_vwh[CCH*CCH], g_vwl[CCH*CCH];
__device__ __align__(16) bf16 g_Qh[FSZ], g_Ql[FSZ], g_Kh[FSZ], g_Kl[FSZ];

__device__ __forceinline__ uint32_t smem_u32(const void* p) {
    uint32_t a;
    asm("{ .reg .u64 t; cvta.to.shared.u64 t, %1; cvt.u32.u64 %0, t; }"
        : "=r"(a) : "l"(p));
    return a;
}
__device__ __forceinline__ uint32_t pk(bf16 a, bf16 b) {
    return (uint32_t)__bfloat16_as_ushort(a) |
           ((uint32_t)__bfloat16_as_ushort(b) << 16);
}
__device__ __forceinline__ void spl(float x, bf16& h, bf16& l) {
    h = __float2bfloat16(x);
    l = __float2bfloat16(x - __bfloat162float(h));
}
__device__ __forceinline__ void wr_bf(bf16* H, bf16* L, size_t off,
                                      float a, float b) {
    bf16 h0, l0, h1, l1;
    spl(a, h0, l0); spl(b, h1, l1);
    *(uint32_t*)(H + off) = pk(h0, h1);
    *(uint32_t*)(L + off) = pk(l0, l1);
}
__device__ __forceinline__ float rna32(float x) {
    uint32_t u;
    asm("cvt.rna.tf32.f32 %0, %1;" : "=r"(u) : "f"(x));
    return __uint_as_float(u);
}

#define CPA(d, s)     asm volatile("cp.async.cg.shared.global [%0], [%1], 16;" :: "r"(d), "l"(s))
#define CPA_COMMIT()  asm volatile("cp.async.commit_group;")
#define CPA_WAIT0()   asm volatile("cp.async.wait_group 0;")
#define CPA_WAIT1()   asm volatile("cp.async.wait_group 1;")

#define LDMX4(R, addr) \
    asm volatile("ldmatrix.sync.aligned.m8n8.x4.shared.b16 {%0,%1,%2,%3}, [%4];" \
        : "=r"((R)[0]), "=r"((R)[1]), "=r"((R)[2]), "=r"((R)[3]) : "r"(addr))
#define LDMX4T(R, addr) \
    asm volatile("ldmatrix.sync.aligned.m8n8.x4.trans.shared.b16 {%0,%1,%2,%3}, [%4];" \
        : "=r"((R)[0]), "=r"((R)[1]), "=r"((R)[2]), "=r"((R)[3]) : "r"(addr))
#define MMA16816(d, a, b) \
    asm volatile("mma.sync.aligned.m16n8k16.row.col.f32.bf16.bf16.f32 " \
        "{%0,%1,%2,%3}, {%4,%5,%6,%7}, {%8,%9}, {%0,%1,%2,%3};" \
        : "+f"((d)[0]), "+f"((d)[1]), "+f"((d)[2]), "+f"((d)[3]) \
        : "r"((a)[0]), "r"((a)[1]), "r"((a)[2]), "r"((a)[3]), \
          "r"((b)[0]), "r"((b)[1]))
#define MMATF32(d, a, b) \
    asm volatile("mma.sync.aligned.m16n8k8.row.col.f32.tf32.tf32.f32 " \
        "{%0,%1,%2,%3}, {%4,%5,%6,%7}, {%8,%9}, {%0,%1,%2,%3};" \
        : "+f"((d)[0]), "+f"((d)[1]), "+f"((d)[2]), "+f"((d)[3]) \
        : "r"((a)[0]), "r"((a)[1]), "r"((a)[2]), "r"((a)[3]), \
          "r"((b)[0]), "r"((b)[1]))

enum { E_NONE = 0, E_BROW = 1 };

// ===========================================================================
// converters
// ===========================================================================
__global__ __launch_bounds__(256) void k_cvt(const float* __restrict__ X,
                                             bf16* __restrict__ H,
                                             bf16* __restrict__ L, int n4)
{
    const int i = blockIdx.x * 256 + threadIdx.x;
    if (i >= n4) return;
    float4 v = *(const float4*)(X + (size_t)i * 4);
    bf16 h0,l0,h1,l1,h2,l2,h3,l3;
    spl(v.x,h0,l0); spl(v.y,h1,l1); spl(v.z,h2,l2); spl(v.w,h3,l3);
    *(uint2*)(H + (size_t)i * 4) = make_uint2(pk(h0,h1), pk(h2,h3));
    *(uint2*)(L + (size_t)i * 4) = make_uint2(pk(l0,l1), pk(l2,l3));
}
__global__ __launch_bounds__(256) void k_cvt32(const float* __restrict__ X,
                                               float* __restrict__ T, int n4)
{
    const int i = blockIdx.x * 256 + threadIdx.x;
    if (i >= n4) return;
    float4 v = *(const float4*)(X + (size_t)i * 4);
    v.x = rna32(v.x); v.y = rna32(v.y); v.z = rna32(v.z); v.w = rna32(v.w);
    *(float4*)(T + (size_t)i * 4) = v;
}

// ===========================================================================
// bf16 split HMMA GEMM (QKV path), 128x64 tile, 3-stage cp.async
// ===========================================================================
template <int EPI, bool OBF, bool OT32>
__global__ __launch_bounds__(256, 2) void k_mm(
    const bf16* __restrict__ Ah, const bf16* __restrict__ Al,
    size_t Abs, int lda,
    const bf16* __restrict__ Bh, const bf16* __restrict__ Bl,
    size_t Bbs, int ldb, int Ktot,
    bf16* __restrict__ Dh, bf16* __restrict__ Dl,
    float* __restrict__ Dt,
    size_t Dbs, int ldd,
    const float* __restrict__ bias)
{
    extern __shared__ char sm[];
    constexpr int ASZ = BMT * AK_PAD * 2;
    constexpr int BSZ = BKT * BN_PAD * 2;
    constexpr int STG = 2 * ASZ + 2 * BSZ;

    const int tid = threadIdx.x, wid = tid >> 5, lane = tid & 31;
    const int wm = wid & 3, wn = wid >> 2;
    const int colT = blockIdx.x * BNT, rowT = blockIdx.y * BMT, bz = blockIdx.z;
    const uint32_t su = smem_u32(sm);

    const bf16* Ah_b = Ah + (size_t)bz * Abs;
    const bf16* Al_b = Al + (size_t)bz * Abs;
    const bf16* Bh_b = Bh + (size_t)bz * Bbs;
    const bf16* Bl_b = Bl + (size_t)bz * Bbs;

    float acc[2][4][4];
    #pragma unroll
    for (int i = 0; i < 2; i++)
        #pragma unroll
        for (int j = 0; j < 4; j++)
            #pragma unroll
            for (int q = 0; q < 4; q++) acc[i][j][q] = 0.f;

    auto cpa = [&](int k0, int s) {
        const uint32_t base = su + s * STG;
        #pragma unroll
        for (int i = 0; i < 2; i++) {
            const int idx = tid + (i << 8);
            const int row = idx >> 2, c4 = idx & 3;
            const size_t so = (size_t)(rowT + row) * lda + k0 + c4 * 8;
            const uint32_t d = base + (uint32_t)row * (AK_PAD * 2) + c4 * 16;
            CPA(d, Ah_b + so);
            CPA(d + ASZ, Al_b + so);
        }
        const int row = tid >> 3, c8 = tid & 7;
        const size_t so = (size_t)(k0 + row) * ldb + colT + c8 * 8;
        const uint32_t d = base + 2 * ASZ + (uint32_t)row * (BN_PAD * 2) + c8 * 16;
        CPA(d, Bh_b + so);
        CPA(d + BSZ, Bl_b + so);
    };

    const int mtx = lane >> 3, r8 = lane & 7;
    uint32_t aoff[2][2];
    #pragma unroll
    for (int mi = 0; mi < 2; mi++)
        #pragma unroll
        for (int ks = 0; ks < 2; ks++) {
            const int row = wm * 32 + mi * 16 + (mtx & 1) * 8 + r8;
            const int kc  = ks * 16 + (mtx >> 1) * 8;
            aoff[mi][ks] = (uint32_t)row * (AK_PAD * 2) + kc * 2;
        }
    uint32_t boff[2][2];
    #pragma unroll
    for (int ni2 = 0; ni2 < 2; ni2++)
        #pragma unroll
        for (int ks = 0; ks < 2; ks++) {
            const int kb = ks * 16 + (mtx & 1) * 8 + r8;
            const int nb = wn * 32 + ni2 * 16 + (mtx >> 1) * 8;
            boff[ni2][ks] = (uint32_t)kb * (BN_PAD * 2) + nb * 2;
        }

    const int nch = Ktot / BKT;
    cpa(0, 0);
    CPA_COMMIT();
    if (nch > 1) { cpa(BKT, 1); CPA_COMMIT(); }

    int s = 0;
    for (int i = 0; i < nch; i++) {
        if (i + 1 < nch) CPA_WAIT1(); else CPA_WAIT0();
        __syncthreads();
        if (i + 2 < nch) {
            int s2 = s + 2; if (s2 >= 3) s2 -= 3;
            cpa((i + 2) * BKT, s2);
            CPA_COMMIT();
        }
        const uint32_t aHi = su + s * STG;
        const uint32_t aLo = aHi + ASZ;
        const uint32_t bHi = aHi + 2 * ASZ;
        const uint32_t bLo = bHi + BSZ;

        #pragma unroll
        for (int ks = 0; ks < 2; ks++) {
            uint32_t ah[2][4], al[2][4];
            #pragma unroll
            for (int mi = 0; mi < 2; mi++) {
                LDMX4(ah[mi], aHi + aoff[mi][ks]);
                LDMX4(al[mi], aLo + aoff[mi][ks]);
            }
            #pragma unroll
            for (int ni2 = 0; ni2 < 2; ni2++) {
                uint32_t bh[4], bl[4];
                LDMX4T(bh, bHi + boff[ni2][ks]);
                LDMX4T(bl, bLo + boff[ni2][ks]);
                #pragma unroll
                for (int mi = 0; mi < 2; mi++) {
                    #pragma unroll
                    for (int nf = 0; nf < 2; nf++) {
                        float* ac = acc[mi][ni2 * 2 + nf];
                        MMA16816(ac, ah[mi], bh + nf * 2);
                        MMA16816(ac, ah[mi], bl + nf * 2);
                        MMA16816(ac, al[mi], bh + nf * 2);
                    }
                }
            }
        }
        s += 1; if (s >= 3) s = 0;
    }

    #pragma unroll
    for (int mi = 0; mi < 2; mi++) {
        const int r = rowT + wm * 32 + mi * 16 + (lane >> 2);
        float ba = 0.f, bb_ = 0.f;
        if (EPI == E_BROW) { ba = bias[r]; bb_ = bias[r + 8]; }
        const size_t ro0 = (size_t)bz * Dbs + (size_t)r * ldd;
        const size_t ro1 = ro0 + 8 * (size_t)ldd;
        #pragma unroll
        for (int ni = 0; ni < 4; ni++) {
            const int c = colT + wn * 32 + ni * 8 + ((lane & 3) << 1);
            float v0 = acc[mi][ni][0] + ba, v1 = acc[mi][ni][1] + ba;
            float v2 = acc[mi][ni][2] + bb_, v3 = acc[mi][ni][3] + bb_;
            if (OBF) {
                wr_bf(Dh, Dl, ro0 + c, v0, v1);
                wr_bf(Dh, Dl, ro1 + c, v2, v3);
            }
            if (OT32) {
                *(float2*)(Dt + ro0 + c) = make_float2(rna32(v0), rna32(v1));
                *(float2*)(Dt + ro1 + c) = make_float2(rna32(v2), rna32(v3));
            }
        }
    }
}

// ===========================================================================
// Scores GEMM: D[n][m] = sum_c K[c][n]*Q[c][m], 128x128 block tile,
// warp tile 32x64, acc 64 regs, 3-stage cp.async. A=K planes, B=Q planes,
// both [32][136]-pad bf16 k-major tiles.
// ===========================================================================
#define SASZ (32 * SC_PAD * 2)      // 8704 per plane
#define SSTG (4 * SASZ)             // Ahi Alo Bhi Blo = 34816

__global__ __launch_bounds__(256, 2) void k_sc(
    const bf16* __restrict__ Ah, const bf16* __restrict__ Al,  // K planes
    const bf16* __restrict__ Bh, const bf16* __restrict__ Bl,  // Q planes
    float* __restrict__ D)
{
    extern __shared__ char sm[];
    const int tid = threadIdx.x, wid = tid >> 5, lane = tid & 31;
    const int wm = wid & 3, wn = wid >> 2;
    const int colT = blockIdx.x * 128, rowT = blockIdx.y * 128, bz = blockIdx.z;
    const uint32_t su = smem_u32(sm);

    const bf16* Ah_b = Ah + (size_t)bz * ((size_t)CCH * NPIX);
    const bf16* Al_b = Al + (size_t)bz * ((size_t)CCH * NPIX);
    const bf16* Bh_b = Bh + (size_t)bz * ((size_t)CCH * NPIX);
    const bf16* Bl_b = Bl + (size_t)bz * ((size_t)CCH * NPIX);

    float acc[2][8][4];
    #pragma unroll
    for (int i = 0; i < 2; i++)
        #pragma unroll
        for (int j = 0; j < 8; j++)
            #pragma unroll
            for (int q = 0; q < 4; q++) acc[i][j][q] = 0.f;

    // loads: each plane = 32 rows x 256B; 512 16B-chunks; 2 per thread
    auto cpa = [&](int k0, int s) {
        const uint32_t base = su + s * SSTG;
        #pragma unroll
        for (int i = 0; i < 2; i++) {
            const int idx = tid + (i << 8);
            const int row = idx >> 4, c16 = idx & 15;
            const uint32_t d = base + (uint32_t)row * (SC_PAD * 2) + c16 * 16;
            const size_t soA = (size_t)(k0 + row) * NPIX + rowT + c16 * 8;
            const size_t soB = (size_t)(k0 + row) * NPIX + colT + c16 * 8;
            CPA(d,            Ah_b + soA);
            CPA(d + SASZ,     Al_b + soA);
            CPA(d + 2 * SASZ, Bh_b + soB);
            CPA(d + 3 * SASZ, Bl_b + soB);
        }
    };

    const int mtx = lane >> 3, r8 = lane & 7;
    uint32_t aoff[2][2];
    #pragma unroll
    for (int mi = 0; mi < 2; mi++)
        #pragma unroll
        for (int ks = 0; ks < 2; ks++) {
            const int kk = ks * 16 + (mtx >> 1) * 8 + r8;
            const int mm = wm * 32 + mi * 16 + (mtx & 1) * 8;
            aoff[mi][ks] = (uint32_t)kk * (SC_PAD * 2) + mm * 2;
        }
    uint32_t boff[4][2];
    #pragma unroll
    for (int ni2 = 0; ni2 < 4; ni2++)
        #pragma unroll
        for (int ks = 0; ks < 2; ks++) {
            const int kb = ks * 16 + (mtx & 1) * 8 + r8;
            const int nb = wn * 64 + ni2 * 16 + (mtx >> 1) * 8;
            boff[ni2][ks] = (uint32_t)kb * (SC_PAD * 2) + nb * 2;
        }

    const int nch = CCH / BKT;    // 8
    cpa(0, 0);
    CPA_COMMIT();
    cpa(BKT, 1);
    CPA_COMMIT();

    int s = 0;
    for (int i = 0; i < nch; i++) {
        if (i + 1 < nch) CPA_WAIT1(); else CPA_WAIT0();
        __syncthreads();
        if (i + 2 < nch) {
            int s2 = s + 2; if (s2 >= 3) s2 -= 3;
            cpa((i + 2) * BKT, s2);
            CPA_COMMIT();
        }
        const uint32_t aHi = su + s * SSTG;
        const uint32_t aLo = aHi + SASZ;
        const uint32_t bHi = aHi + 2 * SASZ;
        const uint32_t bLo = aHi + 3 * SASZ;

        #pragma unroll
        for (int ks = 0; ks < 2; ks++) {
            uint32_t ah[2][4], al[2][4];
            #pragma unroll
            for (int mi = 0; mi < 2; mi++) {
                LDMX4T(ah[mi], aHi + aoff[mi][ks]);
                LDMX4T(al[mi], aLo + aoff[mi][ks]);
            }
            #pragma unroll
            for (int ni2 = 0; ni2 < 4; ni2++) {
                uint32_t bh[4], bl[4];
                LDMX4T(bh, bHi + boff[ni2][ks]);
                LDMX4T(bl, bLo + boff[ni2][ks]);
                #pragma unroll
                for (int mi = 0; mi < 2; mi++) {
                    #pragma unroll
                    for (int nf = 0; nf < 2; nf++) {
                        float* ac = acc[mi][ni2 * 2 + nf];
                        MMA16816(ac, ah[mi], bh + nf * 2);
                        MMA16816(ac, ah[mi], bl + nf * 2);
                        MMA16816(ac, al[mi], bh + nf * 2);
                    }
                }
            }
        }
        s += 1; if (s >= 3) s = 0;
    }

    #pragma unroll
    for (int mi = 0; mi < 2; mi++) {
        const int r = rowT + wm * 32 + mi * 16 + (lane >> 2);
        const size_t ro0 = (size_t)bz * ((size_t)NPIX * NPIX) + (size_t)r * NPIX;
        const size_t ro1 = ro0 + 8 * (size_t)NPIX;
        #pragma unroll
        for (int ni = 0; ni < 8; ni++) {
            const int c = colT + wn * 64 + ni * 8 + ((lane & 3) << 1);
            *(float2*)(D + ro0 + c) = make_float2(acc[mi][ni][0], acc[mi][ni][1]);
            *(float2*)(D + ro1 + c) = make_float2(acc[mi][ni][2], acc[mi][ni][3]);
        }
    }
}

// ===========================================================================
// tf32 tile core (conv32 / av32): A [128][36]fl, B [32][72]fl
// ===========================================================================
#define ASZ32 (128 * 36 * 4)
#define BSZ32 (32 * 72 * 4)
#define STG32 (ASZ32 + BSZ32)

template <bool SECOND>
__global__ __launch_bounds__(256, 2) void k_conv32(
    const float* __restrict__ Wt,
    const float* __restrict__ In,
    const float* __restrict__ bns, const float* __restrict__ bnb,
    const float* __restrict__ bnm, const float* __restrict__ bnv,
    const float* __restrict__ Res,
    float* __restrict__ Out)
{
    extern __shared__ char sm[];
    const int tid = threadIdx.x, wid = tid >> 5, lane = tid & 31;
    const int wm = wid & 3, wn = wid >> 2;
    const int colT = blockIdx.x * BNT, rowT = blockIdx.y * BMT, bz = blockIdx.z;
    const uint32_t su = smem_u32(sm);
    const float* Inb = In + (size_t)bz * (size_t)CCH * NPIX;

    float acc[2][4][4];
    #pragma unroll
    for (int i = 0; i < 2; i++)
        #pragma unroll
        for (int j = 0; j < 4; j++)
            #pragma unroll
            for (int q = 0; q < 4; q++) acc[i][j][q] = 0.f;

    auto cpaA = [&](int k0, int s) {
        const uint32_t base = su + s * STG32;
        #pragma unroll
        for (int i = 0; i < 4; i++) {
            const int idx = tid + (i << 8);
            const int row = idx >> 3, c4 = idx & 7;
            const size_t so = (size_t)(rowT + row) * KCONV + k0 + c4 * 4;
            CPA(base + (uint32_t)row * 144 + c4 * 16, Wt + so);
        }
    };
    float bst[8];
    auto ldB = [&](int k0) {
        #pragma unroll
        for (int j = 0; j < 2; j++) {
            const int kg = k0 + (tid >> 4) + j * 16;
            const int c  = kg / 9;
            const int r  = kg - c * 9;
            const int ky = r / 3;
            const int kx = r - ky * 3;
            const size_t cb = (size_t)c * NPIX;
            #pragma unroll
            for (int u = 0; u < 4; u++) {
                const int p = colT + ((tid & 15) << 2) + u;
                const int y = p / WWW, x = p - y * WWW;
                const int sy = y + ky - 1, sx = x + kx - 1;
                const bool ok = (unsigned)sy < (unsigned)HHH &&
                                (unsigned)sx < (unsigned)WWW;
                bst[j * 4 + u] = ok ? Inb[cb + sy * WWW + sx] : 0.f;
            }
        }
    };
    auto stsB = [&](int s) {
        const uint32_t base = su + s * STG32 + ASZ32;
        #pragma unroll
        for (int j = 0; j < 2; j++) {
            const uint32_t d = base + (uint32_t)((tid >> 4) + j * 16) * 288
                               + ((tid & 15) << 4);
            asm volatile("st.shared.v4.b32 [%0], {%1,%2,%3,%4};"
                :: "r"(d), "r"(__float_as_uint(bst[j*4+0])),
                   "r"(__float_as_uint(bst[j*4+1])),
                   "r"(__float_as_uint(bst[j*4+2])),
                   "r"(__float_as_uint(bst[j*4+3])) : "memory");
        }
    };

    const int gr = lane >> 2, tg = lane & 3;
    uint32_t a0off[2];
    #pragma unroll
    for (int mi = 0; mi < 2; mi++)
        a0off[mi] = (uint32_t)(wm * 32 + mi * 16 + gr) * 144 + tg * 4;
    uint32_t b0off[4];
    #pragma unroll
    for (int ni = 0; ni < 4; ni++)
        b0off[ni] = ASZ32 + (uint32_t)tg * 288
                    + (uint32_t)(wn * 32 + ni * 8 + gr) * 4;

    const int nch = KCONV / BKT;
    cpaA(0, 0);
    CPA_COMMIT();
    ldB(0); stsB(0);
    CPA_WAIT0();
    __syncthreads();

    for (int i = 0; i < nch; i++) {
        const int s = i & 1;
        if (i + 1 < nch) {
            cpaA((i + 1) * BKT, s ^ 1);
            CPA_COMMIT();
            ldB((i + 1) * BKT);
        }
        const uint32_t base = su + s * STG32;
        #pragma unroll
        for (int ks = 0; ks < 4; ks++) {
            uint32_t a[2][4], b[4][2];
            #pragma unroll
            for (int mi = 0; mi < 2; mi++) {
                const uint32_t a0 = base + a0off[mi] + ks * 32;
                asm volatile("ld.shared.b32 %0, [%1];" : "=r"(a[mi][0]) : "r"(a0));
                asm volatile("ld.shared.b32 %0, [%1];" : "=r"(a[mi][1]) : "r"(a0 + 8*144));
                asm volatile("ld.shared.b32 %0, [%1];" : "=r"(a[mi][2]) : "r"(a0 + 16));
                asm volatile("ld.shared.b32 %0, [%1];" : "=r"(a[mi][3]) : "r"(a0 + 8*144 + 16));
            }
            #pragma unroll
            for (int ni = 0; ni < 4; ni++) {
                const uint32_t b0 = base + b0off[ni] + ks * 2304;
                asm volatile("ld.shared.b32 %0, [%1];" : "=r"(b[ni][0]) : "r"(b0));
                asm volatile("ld.shared.b32 %0, [%1];" : "=r"(b[ni][1]) : "r"(b0 + 4*288));
            }
            #pragma unroll
            for (int mi = 0; mi < 2; mi++)
                #pragma unroll
                for (int ni = 0; ni < 4; ni++)
                    MMATF32(acc[mi][ni], a[mi], b[ni]);
        }
        if (i + 1 < nch) { stsB(s ^ 1); CPA_WAIT0(); }
        __syncthreads();
    }

    #pragma unroll
    for (int mi = 0; mi < 2; mi++) {
        const int r = rowT + wm * 32 + mi * 16 + gr;
        const float inva   = bns[r] * rsqrtf(bnv[r] + EPSB);
        const float beta_a = bnb[r] - bnm[r] * inva;
        const float invb   = bns[r + 8] * rsqrtf(bnv[r + 8] + EPSB);
        const float beta_b = bnb[r + 8] - bnm[r + 8] * invb;
        const size_t ro0 = (size_t)bz * ((size_t)CCH * NPIX) + (size_t)r * NPIX;
        const size_t ro1 = ro0 + 8 * (size_t)NPIX;
        const float* rs0 = SECOND ? Res + ro0 : nullptr;
        const float* rs1 = SECOND ? Res + ro1 : nullptr;
        #pragma unroll
        for (int ni = 0; ni < 4; ni++) {
            const int c = colT + wn * 32 + ni * 8 + (tg << 1);
            float v0 = acc[mi][ni][0] * inva + beta_a;
            float v1 = acc[mi][ni][1] * inva + beta_a;
            float v2 = acc[mi][ni][2] * invb + beta_b;
            float v3 = acc[mi][ni][3] * invb + beta_b;
            if (SECOND) {
                float2 f0 = *(const float2*)(rs0 + c);
                float2 f1 = *(const float2*)(rs1 + c);
                v0 = fmaxf(v0 + f0.x, 0.f) + f0.x;
                v1 = fmaxf(v1 + f0.y, 0.f) + f0.y;
                v2 = fmaxf(v2 + f1.x, 0.f) + f1.x;
                v3 = fmaxf(v3 + f1.y, 0.f) + f1.y;
            } else {
                v0 = rna32(fmaxf(v0, 0.f)); v1 = rna32(fmaxf(v1, 0.f));
                v2 = rna32(fmaxf(v2, 0.f)); v3 = rna32(fmaxf(v3, 0.f));
            }
            *(float2*)(Out + ro0 + c) = make_float2(v0, v1);
            *(float2*)(Out + ro1 + c) = make_float2(v2, v3);
        }
    }
}

__global__ __launch_bounds__(256, 2) void k_av32(
    const float* __restrict__ V32,
    const float* __restrict__ At32,
    const float* __restrict__ Fb,
    float* __restrict__ Dfull, float* __restrict__ Dt32)
{
    extern __shared__ char sm[];
    const int tid = threadIdx.x, wid = tid >> 5, lane = tid & 31;
    const int wm = wid & 3, wn = wid >> 2;
    const int colT = blockIdx.x * BNT, rowT = blockIdx.y * BMT, bz = blockIdx.z;
    const uint32_t su = smem_u32(sm);
    const float* Vb = V32  + (size_t)bz * (size_t)CCH * NPIX;
    const float* Ab = At32 + (size_t)bz * (size_t)NPIX * NPIX;

    float acc[2][4][4];
    #pragma unroll
    for (int i = 0; i < 2; i++)
        #pragma unroll
        for (int j = 0; j < 4; j++)
            #pragma unroll
            for (int q = 0; q < 4; q++) acc[i][j][q] = 0.f;

    auto cpa = [&](int k0, int s) {
        const uint32_t base = su + s * STG32;
        #pragma unroll
        for (int i = 0; i < 4; i++) {
            const int idx = tid + (i << 8);
            const int row = idx >> 3, c4 = idx & 7;
            const size_t so = (size_t)(rowT + row) * NPIX + k0 + c4 * 4;
            CPA(base + (uint32_t)row * 144 + c4 * 16, Vb + so);
        }
        #pragma unroll
        for (int i = 0; i < 2; i++) {
            const int idx = tid + (i << 8);
            const int row = idx >> 4, c16 = idx & 15;
            const size_t so = (size_t)(k0 + row) * NPIX + colT + c16 * 4;
            CPA(base + ASZ32 + (uint32_t)row * 288 + c16 * 16, Ab + so);
        }
    };

    const int gr = lane >> 2, tg = lane & 3;
    uint32_t a0off[2];
    #pragma unroll
    for (int mi = 0; mi < 2; mi++)
        a0off[mi] = (uint32_t)(wm * 32 + mi * 16 + gr) * 144 + tg * 4;
    uint32_t b0off[4];
    #pragma unroll
    for (int ni = 0; ni < 4; ni++)
        b0off[ni] = ASZ32 + (uint32_t)tg * 288
                    + (uint32_t)(wn * 32 + ni * 8 + gr) * 4;

    const int nch = NPIX / BKT;
    cpa(0, 0);
    CPA_COMMIT();
    CPA_WAIT0();
    __syncthreads();

    for (int i = 0; i < nch; i++) {
        const int s = i & 1;
        if (i + 1 < nch) {
            cpa((i + 1) * BKT, s ^ 1);
            CPA_COMMIT();
        }
        const uint32_t base = su + s * STG32;
        #pragma unroll
        for (int ks = 0; ks < 4; ks++) {
            uint32_t a[2][4], b[4][2];
            #pragma unroll
            for (int mi = 0; mi < 2; mi++) {
                const uint32_t a0 = base + a0off[mi] + ks * 32;
                asm volatile("ld.shared.b32 %0, [%1];" : "=r"(a[mi][0]) : "r"(a0));
                asm volatile("ld.shared.b32 %0, [%1];" : "=r"(a[mi][1]) : "r"(a0 + 8*144));
                asm volatile("ld.shared.b32 %0, [%1];" : "=r"(a[mi][2]) : "r"(a0 + 16));
                asm volatile("ld.shared.b32 %0, [%1];" : "=r"(a[mi][3]) : "r"(a0 + 8*144 + 16));
            }
            #pragma unroll
            for (int ni = 0; ni < 4; ni++) {
                const uint32_t b0 = base + b0off[ni] + ks * 2304;
                asm volatile("ld.shared.b32 %0, [%1];" : "=r"(b[ni][0]) : "r"(b0));
                asm volatile("ld.shared.b32 %0, [%1];" : "=r"(b[ni][1]) : "r"(b0 + 4*288));
            }
            #pragma unroll
            for (int mi = 0; mi < 2; mi++)
                #pragma unroll
                for (int ni = 0; ni < 4; ni++)
                    MMATF32(acc[mi][ni], a[mi], b[ni]);
        }
        if (i + 1 < nch) CPA_WAIT0();
        __syncthreads();
    }

    #pragma unroll
    for (int mi = 0; mi < 2; mi++) {
        const int r = rowT + wm * 32 + mi * 16 + gr;
        const size_t ro0 = (size_t)bz * ((size_t)CCH * NPIX) + (size_t)r * NPIX;
        const size_t ro1 = ro0 + 8 * (size_t)NPIX;
        const float* rs0 = Fb + ro0;
        const float* rs1 = Fb + ro1;
        #pragma unroll
        for (int ni = 0; ni < 4; ni++) {
            const int c = colT + wn * 32 + ni * 8 + (tg << 1);
            float2 f0 = *(const float2*)(rs0 + c);
            float2 f1 = *(const float2*)(rs1 + c);
            const float v0 = acc[mi][ni][0] + f0.x;
            const float v1 = acc[mi][ni][1] + f0.y;
            const float v2 = acc[mi][ni][2] + f1.x;
            const float v3 = acc[mi][ni][3] + f1.y;
            *(float2*)(Dfull + ro0 + c) = make_float2(v0, v1);
            *(float2*)(Dfull + ro1 + c) = make_float2(v2, v3);
            *(float2*)(Dt32 + ro0 + c) = make_float2(rna32(v0), rna32(v1));
            *(float2*)(Dt32 + ro1 + c) = make_float2(rna32(v2), rna32(v3));
        }
    }
}

__global__ __launch_bounds__(256) void k_softmax(float* __restrict__ S)
{
    float* p = S + (size_t)blockIdx.x * NPIX;
    const int tid = threadIdx.x;
    float v[9];
    float mx = -1e30f;
    #pragma unroll
    for (int i = 0; i < 9; i++) {
        v[i] = p[tid + (i << 8)];
        mx = fmaxf(mx, v[i]);
    }
    __shared__ float red[8];
    #pragma unroll
    for (int o = 16; o > 0; o >>= 1)
        mx = fmaxf(mx, __shfl_xor_sync(0xffffffffu, mx, o));
    if ((tid & 31) == 0) red[tid >> 5] = mx;
    __syncthreads();
    float m2 = red[0];
    #pragma unroll
    for (int i = 1; i < 8; i++) m2 = fmaxf(m2, red[i]);
    __syncthreads();
    float s = 0.f;
    #pragma unroll
    for (int i = 0; i < 9; i++) { v[i] = __expf(v[i] - m2); s += v[i]; }
    #pragma unroll
    for (int o = 16; o > 0; o >>= 1)
        s += __shfl_xor_sync(0xffffffffu, s, o);
    if ((tid & 31) == 0) red[tid >> 5] = s;
    __syncthreads();
    float s2 = 0.f;
    #pragma unroll
    for (int i = 0; i < 8; i++) s2 += red[i];
    const float inv = 1.0f / s2;
    #pragma unroll
    for (int i = 0; i < 9; i++)
        p[tid + (i << 8)] = rna32(v[i] * inv);
}

// ===========================================================================
// Host launcher
// ===========================================================================
extern "C" void kernel_launch(void* const* d_in, const int* in_sizes, int n_in,
                              void* d_out, int out_size)
{
    (void)in_sizes; (void)n_in; (void)out_size;
    const float* F_b  = (const float*)d_in[0];
    const float* F_a  = (const float*)d_in[1];
    const float* qw   = (const float*)d_in[2];
    const float* qb   = (const float*)d_in[3];
    const float* kw   = (const float*)d_in[4];
    const float* kb   = (const float*)d_in[5];
    const float* vw   = (const float*)d_in[6];
    const float* vb   = (const float*)d_in[7];
    const float* c1w  = (const float*)d_in[8];
    const float* bn1s = (const float*)d_in[9];
    const float* bn1b = (const float*)d_in[10];
    const float* bn1m = (const float*)d_in[11];
    const float* bn1v = (const float*)d_in[12];
    const float* c2w  = (const float*)d_in[13];
    const float* bn2s = (const float*)d_in[14];
    const float* bn2b = (const float*)d_in[15];
    const float* bn2m = (const float*)d_in[16];
    const float* bn2v = (const float*)d_in[17];
    float* out = (float*)d_out;

    float *scores, *fused, *ft32, *tt32, *vt32, *c1t, *c2t;
    bf16 *Fbh,*Fbl,*Fah,*Fal,*qwh,*qwl,*kwh,*kwl,*vwh,*vwl;
    bf16 *Qh,*Ql,*Kh,*Kl;
    cudaGetSymbolAddress((void**)&scores, g_scores);
    cudaGetSymbolAddress((void**)&fused,  g_fused);
    cudaGetSymbolAddress((void**)&ft32,   g_ft32);
    cudaGetSymbolAddress((void**)&tt32,   g_tt32);
    cudaGetSymbolAddress((void**)&vt32,   g_vt32);
    cudaGetSymbolAddress((void**)&c1t,    g_c1t);
    cudaGetSymbolAddress((void**)&c2t,    g_c2t);
    cudaGetSymbolAddress((void**)&Fbh, g_Fbh); cudaGetSymbolAddress((void**)&Fbl, g_Fbl);
    cudaGetSymbolAddress((void**)&Fah, g_Fah); cudaGetSymbolAddress((void**)&Fal, g_Fal);
    cudaGetSymbolAddress((void**)&qwh, g_qwh); cudaGetSymbolAddress((void**)&qwl, g_qwl);
    cudaGetSymbolAddress((void**)&kwh, g_kwh); cudaGetSymbolAddress((void**)&kwl, g_kwl);
    cudaGetSymbolAddress((void**)&vwh, g_vwh); cudaGetSymbolAddress((void**)&vwl, g_vwl);
    cudaGetSymbolAddress((void**)&Qh,  g_Qh);  cudaGetSymbolAddress((void**)&Ql,  g_Ql);
    cudaGetSymbolAddress((void**)&Kh,  g_Kh);  cudaGetSymbolAddress((void**)&Kl,  g_Kl);

    const int STG_MK = 2 * (BMT * AK_PAD * 2) + 2 * (BKT * BN_PAD * 2);
    const int SMEM_MK = 3 * STG_MK;        // 89088
    const int SMEM_SC = 3 * SSTG;          // 104448
    const int SMEM_32 = 2 * STG32;         // 55296

    cudaFuncSetAttribute((const void*)k_mm<E_BROW, true,  false>, cudaFuncAttributeMaxDynamicSharedMemorySize, SMEM_MK);
    cudaFuncSetAttribute((const void*)k_mm<E_BROW, false, true >, cudaFuncAttributeMaxDynamicSharedMemorySize, SMEM_MK);
    cudaFuncSetAttribute((const void*)k_sc,             cudaFuncAttributeMaxDynamicSharedMemorySize, SMEM_SC);
    cudaFuncSetAttribute((const void*)k_av32,           cudaFuncAttributeMaxDynamicSharedMemorySize, SMEM_32);
    cudaFuncSetAttribute((const void*)k_conv32<false>,  cudaFuncAttributeMaxDynamicSharedMemorySize, SMEM_32);
    cudaFuncSetAttribute((const void*)k_conv32<true>,   cudaFuncAttributeMaxDynamicSharedMemorySize, SMEM_32);

    dim3 blk(256);
    dim3 gFeat(NPIX / BNT, CCH / BMT, BBATCH);    // (36, 2, 16)
    dim3 gSc(NPIX / 128, NPIX / 128, BBATCH);     // (18, 18, 16)
    const size_t FS = (size_t)CCH * NPIX;

    // preconvert
    k_cvt<<<(int)(FSZ/4/256), blk>>>(F_b, Fbh, Fbl, (int)(FSZ/4));
    k_cvt<<<(int)(FSZ/4/256), blk>>>(F_a, Fah, Fal, (int)(FSZ/4));
    k_cvt<<<CCH*CCH/4/256, blk>>>(qw, qwh, qwl, CCH*CCH/4);
    k_cvt<<<CCH*CCH/4/256, blk>>>(kw, kwh, kwl, CCH*CCH/4);
    k_cvt<<<CCH*CCH/4/256, blk>>>(vw, vwh, vwl, CCH*CCH/4);
    k_cvt32<<<CCH*KCONV/4/256, blk>>>(c1w, c1t, CCH*KCONV/4);
    k_cvt32<<<CCH*KCONV/4/256, blk>>>(c2w, c2t, CCH*KCONV/4);

    // Q, K (bf16 planes); V (tf32 plane)
    k_mm<E_BROW, true, false><<<gFeat, blk, SMEM_MK>>>(
        qwh, qwl, 0, CCH, Fbh, Fbl, FS, NPIX, CCH,
        Qh, Ql, nullptr, FS, NPIX, qb);
    k_mm<E_BROW, true, false><<<gFeat, blk, SMEM_MK>>>(
        kwh, kwl, 0, CCH, Fah, Fal, FS, NPIX, CCH,
        Kh, Kl, nullptr, FS, NPIX, kb);
    k_mm<E_BROW, false, true><<<gFeat, blk, SMEM_MK>>>(
        vwh, vwl, 0, CCH, Fah, Fal, FS, NPIX, CCH,
        nullptr, nullptr, vt32, FS, NPIX, vb);

    // scores (128x128 tiles)
    k_sc<<<gSc, blk, SMEM_SC>>>(Kh, Kl, Qh, Ql, scores);

    // softmax in place -> tf32 attn
    k_softmax<<<BBATCH * NPIX, blk>>>(scores);

    // fused = V @ attn + F_b
    k_av32<<<gFeat, blk, SMEM_32>>>(vt32, scores, F_b, fused, ft32);

    // convs
    k_conv32<false><<<gFeat, blk, SMEM_32>>>(
        c1t, ft32, bn1s, bn1b, bn1m, bn1v, nullptr, tt32);
    k_conv32<true><<<gFeat, blk, SMEM_32>>>(
        c2t, tt32, bn2s, bn2b, bn2m, bn2v, fused, out);
}